// round 5
// baseline (speedup 1.0000x reference)
#include <cuda_runtime.h>
#include <math.h>
#include <stdint.h>

// ---------------- problem constants ----------------
#define Nn 4096
#define Dd 64
#define HKk 256
#define BM 128
#define BN 128
#define NRB 32
#define NCB 4
#define CHUNK 1024
#define TPC 8
#define OUTPLANE 262144
#define L2E10 14.426950408889634f   // 10 * log2(e)
#define LN2 0.6931471805599453f

typedef unsigned long long ull;

// ---------------- static device scratch ----------------
__device__ float g_zf[Nn*Dd];
__device__ float g_zf_hi[Nn*Dd], g_zf_lo[Nn*Dd];   // scaled by 2
__device__ float g_zs_hi[Nn*Dd], g_zs_lo[Nn*Dd];
__device__ float g_zf2[Nn], g_zs2[Nn], g_phi1[Nn], g_phi2[Nn];
__device__ float g_w1m[Dd], g_w2m[Dd], g_b1m, g_b2m;
__device__ unsigned g_aph1, g_aph2;
__device__ float g_r_m[NCB*Nn], g_r_s[NCB*Nn], g_r_bc[NCB*Nn];
__device__ int   g_r_bj[NCB*Nn];
__device__ float g_c_m[NRB*Nn], g_c_s[NRB*Nn];
__device__ int   g_idx[Nn];
__device__ float g_lse1[Nn], g_lse2[Nn];

// ---------------- f32x2 packed helpers ----------------
#define FMA2(d,a,b,c) asm("fma.rn.f32x2 %0, %1, %2, %3;" : "=l"(d) : "l"(a), "l"(b), "l"(c))
#define ADD2(d,a,b)   asm("add.rn.f32x2 %0, %1, %2;"     : "=l"(d) : "l"(a), "l"(b))
#define MUL2(d,a,b)   asm("mul.rn.f32x2 %0, %1, %2;"     : "=l"(d) : "l"(a), "l"(b))

__device__ __forceinline__ ull dup2(float x) {
    ull r; asm("mov.b64 %0, {%1, %1};" : "=l"(r) : "f"(x)); return r;
}
__device__ __forceinline__ ull pk2(float lo, float hi) {
    ull r; asm("mov.b64 %0, {%1, %2};" : "=l"(r) : "f"(lo), "f"(hi)); return r;
}
__device__ __forceinline__ float2 asf2(ull v) {
    float2 f; asm("mov.b64 {%0, %1}, %2;" : "=f"(f.x), "=f"(f.y) : "l"(v)); return f;
}

struct PC { ull MAG, NMAG, NEG1, C5, C4, C3, C2, C1, ONE, L2; };
__device__ __forceinline__ PC make_pc() {
    PC K;
    K.MAG  = dup2(12582912.0f);
    K.NMAG = dup2(-12582912.0f);
    K.NEG1 = dup2(-1.0f);
    K.C5   = dup2(0.00133335581f);
    K.C4   = dup2(0.00961812910f);
    K.C3   = dup2(0.0555041087f);
    K.C2   = dup2(0.240226507f);
    K.C1   = dup2(0.693147180f);
    K.ONE  = dup2(1.0f);
    K.L2   = dup2(L2E10);
    return K;
}

__device__ __forceinline__ void pexp2acc(ull &acc, ull t, const PC& K) {
    ull tb; ADD2(tb, t, K.MAG);
    ull rr; ADD2(rr, tb, K.NMAG);
    ull f;  FMA2(f, rr, K.NEG1, t);
    ull p = K.C5;
    FMA2(p, p, f, K.C4);
    FMA2(p, p, f, K.C3);
    FMA2(p, p, f, K.C2);
    FMA2(p, p, f, K.C1);
    FMA2(p, p, f, K.ONE);
    int elo = (int)(unsigned)tb         + (127 - 0x4B400000);
    int ehi = (int)(unsigned)(tb >> 32) + (127 - 0x4B400000);
    elo = elo < 0 ? 0 : elo;
    ehi = ehi < 0 ? 0 : ehi;
    ull sc = pk2(__int_as_float(elo << 23), __int_as_float(ehi << 23));
    FMA2(acc, p, sc, acc);
}

__device__ __forceinline__ float fexp2(float x) {
    float t  = fmaxf(x, -126.0f);
    float tb = t + 12582912.0f;
    int   ni = __float_as_int(tb);
    float r  = tb - 12582912.0f;
    float f  = t - r;
    float p  = 0.00133335581f;
    p = fmaf(p, f, 0.00961812910f);
    p = fmaf(p, f, 0.0555041087f);
    p = fmaf(p, f, 0.240226507f);
    p = fmaf(p, f, 0.693147180f);
    p = fmaf(p, f, 1.0f);
    float sc = __int_as_float((ni + (127 - 0x4B400000)) << 23);
    return p * sc;
}

__device__ __forceinline__ unsigned fenc(float f) {
    unsigned u = __float_as_uint(f);
    return (u & 0x80000000u) ? ~u : (u | 0x80000000u);
}
__device__ __forceinline__ float fdec(unsigned u) {
    return (u & 0x80000000u) ? __uint_as_float(u & 0x7fffffffu) : __uint_as_float(~u);
}

__device__ __forceinline__ float tf32_hi(float x) {
    uint32_t h; asm("cvt.rna.tf32.f32 %0, %1;" : "=r"(h) : "f"(x));
    return __uint_as_float(h);
}

// mma.sync m16n8k8 tf32 (sm_80+ baseline — works on plain sm_100)
__device__ __forceinline__ void mma8(float* d, const uint4& a, const uint2& b) {
    asm("mma.sync.aligned.m16n8k8.row.col.f32.tf32.tf32.f32 "
        "{%0,%1,%2,%3}, {%4,%5,%6,%7}, {%8,%9}, {%0,%1,%2,%3};"
        : "+f"(d[0]), "+f"(d[1]), "+f"(d[2]), "+f"(d[3])
        : "r"(a.x), "r"(a.y), "r"(a.z), "r"(a.w), "r"(b.x), "r"(b.y));
}

// ---------------- smem layout (byte offsets from 1024-aligned base) ----------------
#define OFF_AHI 0
#define OFF_ALO 32768
#define OFF_BHI 65536
#define OFF_BLO 98304
#define OFF_NZF2 131072
#define OFF_LP2  131584
#define OFF_NZS2 132096
#define OFF_LP1  132608
#define OFF_COLM 133120
#define OFF_COLS 133632
#define OFF_ROWM 134144
#define OFF_ROWS 136192
#define OFF_ROWB 138240
#define OFF_ROWJ 140288
#define SMEM_BYTES (142336 + 1024)

// ---------------- k0 ----------------
__global__ void k0(const float* __restrict__ w1, const float* __restrict__ b1,
                   const float* __restrict__ w2, const float* __restrict__ b2) {
    int d = threadIdx.x;
    if (d < Dd) {
        float s1 = 0.f, s2 = 0.f;
        for (int k = 0; k < HKk; ++k) { s1 += w1[d*HKk + k]; s2 += w2[d*HKk + k]; }
        g_w1m[d] = s1 / (float)HKk;
        g_w2m[d] = s2 / (float)HKk;
    }
    if (d == 0) { float s = 0.f; for (int k = 0; k < HKk; ++k) s += b1[k]; g_b1m = s / (float)HKk; g_aph1 = 0u; }
    if (d == 1) { float s = 0.f; for (int k = 0; k < HKk; ++k) s += b2[k]; g_b2m = s / (float)HKk; g_aph2 = 0u; }
}

// ---------------- k_tr ----------------
__global__ void k_tr(const float* __restrict__ z) {
    __shared__ float t[32][33];
    int bx = blockIdx.x, by = blockIdx.y;
    int x = bx*32 + threadIdx.x;
    #pragma unroll
    for (int q = 0; q < 4; ++q) {
        int row = by*32 + threadIdx.y + q*8;
        t[threadIdx.y + q*8][threadIdx.x] = z[row*256 + x];
    }
    __syncthreads();
    #pragma unroll
    for (int q = 0; q < 4; ++q) {
        int col = bx*32 + threadIdx.y + q*8;
        int row = by*32 + threadIdx.x;
        g_zf[col*1024 + row] = t[threadIdx.x][threadIdx.y + q*8];
    }
}

// ---------------- k1: zs, hi/lo tf32 splits (A side scaled x2), norms, phi ----------------
__global__ void k1(const float* __restrict__ codebook, const float* __restrict__ noise) {
    int warp = threadIdx.x >> 5, lane = threadIdx.x & 31;
    int row = blockIdx.x*4 + warp;
    const float* crow = codebook + (row >> 3) * (2*Dd);
    const float* nrow = noise + row*Dd;
    const float* frow = g_zf + row*Dd;
    float zs2 = 0.f, p1 = 0.f, zf2 = 0.f, p2 = 0.f;
    #pragma unroll
    for (int q = 0; q < 2; ++q) {
        int d = lane + q*32;
        float mu  = crow[d];
        float cov = expf(crow[Dd + d]);
        float zs  = mu + cov * nrow[d];
        float zh = tf32_hi(zs);
        g_zs_hi[row*Dd + d] = zh;
        g_zs_lo[row*Dd + d] = tf32_hi(zs - zh);
        zs2 += zs*zs;
        p1  += zs * g_w1m[d];
        float zf = frow[d];
        float fh = tf32_hi(zf);
        g_zf_hi[row*Dd + d] = 2.0f * fh;
        g_zf_lo[row*Dd + d] = 2.0f * tf32_hi(zf - fh);
        zf2 += zf*zf;
        p2  += zf * g_w2m[d];
    }
    #pragma unroll
    for (int o = 16; o > 0; o >>= 1) {
        zs2 += __shfl_xor_sync(0xffffffffu, zs2, o);
        p1  += __shfl_xor_sync(0xffffffffu, p1,  o);
        zf2 += __shfl_xor_sync(0xffffffffu, zf2, o);
        p2  += __shfl_xor_sync(0xffffffffu, p2,  o);
    }
    if (lane == 0) {
        float phi1 = p1 + g_b1m, phi2 = p2 + g_b2m;
        g_zs2[row] = zs2;  g_phi1[row] = phi1;
        g_zf2[row] = zf2;  g_phi2[row] = phi2;
        atomicMax(&g_aph1, fenc(phi1));
        atomicMax(&g_aph2, fenc(phi2));
    }
}

// ---------------- k2: mma.sync tf32x3 fused GEMM + argmax + LSEs ----------------
__global__ void __launch_bounds__(256, 1) k2() {
    extern __shared__ char smem_raw[];
    char* sb = (char*)(((uintptr_t)smem_raw + 1023) & ~(uintptr_t)1023);

    const int tid  = threadIdx.x;
    const int lane = tid & 31, wid = tid >> 5;
    const int rw = wid >> 2, cw = wid & 3;     // warp row-half (0..1), col-quarter (0..3)
    const int q  = lane & 3,  g  = lane >> 2;  // thread-in-group, group
    const int rb = blockIdx.x, cb = blockIdx.y;
    const int i0 = rb * BM;
    const float S1g = L2E10 * fdec(g_aph1);
    const float S2g = L2E10 * fdec(g_aph2);
    const PC K = make_pc();

    float* nzf2s = (float*)(sb + OFF_NZF2);
    float* lp2s  = (float*)(sb + OFF_LP2);
    float* nzs2s = (float*)(sb + OFF_NZS2);
    float* lp1s  = (float*)(sb + OFF_LP1);
    float* colm  = (float*)(sb + OFF_COLM);
    float* colsm = (float*)(sb + OFF_COLS);
    float* rowm  = (float*)(sb + OFF_ROWM);
    float* rowss = (float*)(sb + OFF_ROWS);
    float* rowb  = (float*)(sb + OFF_ROWB);
    int*   rowj  = (int*)  (sb + OFF_ROWJ);

    // ---- stage A fragments (fragment-permuted, once) ----
    {
        float4* Ah = (float4*)(sb + OFF_AHI);
        float4* Al = (float4*)(sb + OFF_ALO);
        for (int t2 = tid; t2 < 2048; t2 += 256) {
            int kt = t2 >> 8, mt = (t2 >> 5) & 7, l = t2 & 31;
            int r0 = (i0 + mt*16 + (l >> 2)) * 64;
            int r8 = r0 + 8*64;
            int c0 = kt*8 + (l & 3);
            float4 v;
            v.x = g_zf_hi[r0 + c0];
            v.y = g_zf_hi[r8 + c0];
            v.z = g_zf_hi[r0 + c0 + 4];
            v.w = g_zf_hi[r8 + c0 + 4];
            Ah[t2] = v;
            v.x = g_zf_lo[r0 + c0];
            v.y = g_zf_lo[r8 + c0];
            v.z = g_zf_lo[r0 + c0 + 4];
            v.w = g_zf_lo[r8 + c0 + 4];
            Al[t2] = v;
        }
        if (tid < 128) {
            nzf2s[tid] = -g_zf2[i0 + tid];
            lp2s[tid]  = L2E10 * g_phi2[i0 + tid];
        }
    }
    __syncthreads();

    // hoisted row constants: slot = m*2 + h, row = (rw*4+m)*16 + h*8 + g
    float nzf2row[8], lp2row[8];
    #pragma unroll
    for (int m = 0; m < 4; ++m)
        #pragma unroll
        for (int h = 0; h < 2; ++h) {
            int row = (rw*4 + m)*16 + h*8 + g;
            nzf2row[m*2+h] = nzf2s[row];
            lp2row[m*2+h]  = lp2s[row];
        }

    // row state
    float bq[8], shift[8]; int bj[8]; ull rs2[8];
    #pragma unroll
    for (int s = 0; s < 8; ++s) { bq[s] = -3e38f; shift[s] = -1e30f; bj[s] = 0x7fffffff; rs2[s] = 0ull; }

    for (int t = 0; t < TPC; ++t) {
        const int j0 = cb*CHUNK + t*BN;

        __syncthreads();   // previous tile's B/col-scratch readers done
        // ---- stage B fragments for this tile ----
        {
            float2* Bh = (float2*)(sb + OFF_BHI);
            float2* Bl = (float2*)(sb + OFF_BLO);
            for (int t2 = tid; t2 < 4096; t2 += 256) {
                int kt = t2 >> 9, nt = (t2 >> 5) & 15, l = t2 & 31;
                int n0 = (j0 + nt*8 + (l >> 2)) * 64;
                int ck = kt*8 + (l & 3);
                float2 v;
                v.x = g_zs_hi[n0 + ck];
                v.y = g_zs_hi[n0 + ck + 4];
                Bh[t2] = v;
                v.x = g_zs_lo[n0 + ck];
                v.y = g_zs_lo[n0 + ck + 4];
                Bl[t2] = v;
            }
            if (tid < 128) {
                nzs2s[tid] = -g_zs2[j0 + tid];
                lp1s[tid]  = L2E10 * g_phi1[j0 + tid];
            }
        }
        __syncthreads();

        // ---- GEMM: 3-split tf32 mma ----
        float d[4][4][4];
        #pragma unroll
        for (int m = 0; m < 4; ++m)
            #pragma unroll
            for (int n = 0; n < 4; ++n)
                #pragma unroll
                for (int e = 0; e < 4; ++e) d[m][n][e] = 0.f;

        const uint4* Ah = (const uint4*)(sb + OFF_AHI);
        const uint4* Al = (const uint4*)(sb + OFF_ALO);
        const uint2* Bh = (const uint2*)(sb + OFF_BHI);
        const uint2* Bl = (const uint2*)(sb + OFF_BLO);

        #pragma unroll
        for (int kt = 0; kt < 8; ++kt) {
            uint4 ah[4], al[4];
            uint2 bh[4], bl[4];
            #pragma unroll
            for (int m = 0; m < 4; ++m) ah[m] = Ah[(kt*8 + rw*4 + m)*32 + lane];
            #pragma unroll
            for (int n = 0; n < 4; ++n) bh[n] = Bh[(kt*16 + cw*4 + n)*32 + lane];
            #pragma unroll
            for (int m = 0; m < 4; ++m)
                #pragma unroll
                for (int n = 0; n < 4; ++n) mma8(d[m][n], ah[m], bh[n]);
            #pragma unroll
            for (int m = 0; m < 4; ++m) al[m] = Al[(kt*8 + rw*4 + m)*32 + lane];
            #pragma unroll
            for (int m = 0; m < 4; ++m)
                #pragma unroll
                for (int n = 0; n < 4; ++n) mma8(d[m][n], al[m], bh[n]);
            #pragma unroll
            for (int n = 0; n < 4; ++n) bl[n] = Bl[(kt*16 + cw*4 + n)*32 + lane];
            #pragma unroll
            for (int m = 0; m < 4; ++m)
                #pragma unroll
                for (int n = 0; n < 4; ++n) mma8(d[m][n], ah[m], bl[n]);
        }

        // ---- c2 = D - zf2 - zs2 (in place over d) ----
        ull nzsp[4], lp1p[4];
        const int cbase = cw*32 + 2*q;
        #pragma unroll
        for (int n = 0; n < 4; ++n) {
            nzsp[n] = *(const ull*)(nzs2s + cbase + n*8);
            lp1p[n] = *(const ull*)(lp1s  + cbase + n*8);
        }
        #pragma unroll
        for (int m = 0; m < 4; ++m)
            #pragma unroll
            for (int h = 0; h < 2; ++h) {
                ull rowc = dup2(nzf2row[m*2+h]);
                #pragma unroll
                for (int n = 0; n < 4; ++n) {
                    ull x = pk2(d[m][n][2*h], d[m][n][2*h+1]);
                    ADD2(x, x, nzsp[n]);
                    ADD2(x, x, rowc);
                    float2 f = asf2(x);
                    d[m][n][2*h] = f.x; d[m][n][2*h+1] = f.y;
                }
            }

        // ---- row pass: argmax + shifted exp sums ----
        #pragma unroll
        for (int m = 0; m < 4; ++m)
            #pragma unroll
            for (int h = 0; h < 2; ++h) {
                const int s = m*2 + h;
                float bql = bq[s]; int bjl = bj[s];
                #pragma unroll
                for (int n = 0; n < 4; ++n) {
                    float fx = d[m][n][2*h], fy = d[m][n][2*h+1];
                    int jc = j0 + cw*32 + n*8 + 2*q;
                    if (fx > bql) { bql = fx; bjl = jc; }
                    if (fy > bql) { bql = fy; bjl = jc + 1; }
                }
                bq[s] = bql; bj[s] = bjl;
                float ns = fmaf(L2E10, bql, S1g);
                float rsc = fexp2(shift[s] - ns);
                shift[s] = ns;
                { ull rp = dup2(rsc); MUL2(rs2[s], rs2[s], rp); }
                ull msh = dup2(-ns);
                #pragma unroll
                for (int n = 0; n < 4; ++n) {
                    ull c2p = pk2(d[m][n][2*h], d[m][n][2*h+1]);
                    ull tt; ADD2(tt, lp1p[n], msh);
                    FMA2(tt, c2p, K.L2, tt);
                    pexp2acc(rs2[s], tt, K);
                }
            }

        // ---- col pass: per-tile col max + exp sums ----
        float cmA[4], cmB[4];
        #pragma unroll
        for (int n = 0; n < 4; ++n) { cmA[n] = -3e38f; cmB[n] = -3e38f; }
        #pragma unroll
        for (int m = 0; m < 4; ++m)
            #pragma unroll
            for (int h = 0; h < 2; ++h)
                #pragma unroll
                for (int n = 0; n < 4; ++n) {
                    cmA[n] = fmaxf(cmA[n], d[m][n][2*h]);
                    cmB[n] = fmaxf(cmB[n], d[m][n][2*h+1]);
                }
        float shA[4], shB[4]; ull nshp[4]; ull csp[4];
        #pragma unroll
        for (int n = 0; n < 4; ++n) {
            shA[n] = fmaf(L2E10, cmA[n], S2g);
            shB[n] = fmaf(L2E10, cmB[n], S2g);
            nshp[n] = pk2(-shA[n], -shB[n]);
            csp[n] = 0ull;
        }
        #pragma unroll
        for (int m = 0; m < 4; ++m)
            #pragma unroll
            for (int h = 0; h < 2; ++h) {
                ull lr = dup2(lp2row[m*2+h]);
                #pragma unroll
                for (int n = 0; n < 4; ++n) {
                    ull c2p = pk2(d[m][n][2*h], d[m][n][2*h+1]);
                    ull tt; ADD2(tt, lr, nshp[n]);
                    FMA2(tt, c2p, K.L2, tt);
                    pexp2acc(csp[n], tt, K);
                }
            }
        // unpack to 8 scalar col slots: slot = n*2 + parity
        float shc[8], csc[8];
        #pragma unroll
        for (int n = 0; n < 4; ++n) {
            float2 f = asf2(csp[n]);
            shc[2*n] = shA[n];   csc[2*n] = f.x;
            shc[2*n+1] = shB[n]; csc[2*n+1] = f.y;
        }
        // intra-warp merge over the 8 row-groups (g): xor 4, 8, 16
        #pragma unroll
        for (int mk = 4; mk <= 16; mk <<= 1) {
            #pragma unroll
            for (int s = 0; s < 8; ++s) {
                float om = __shfl_xor_sync(0xffffffffu, shc[s], mk);
                float os = __shfl_xor_sync(0xffffffffu, csc[s], mk);
                if (om > shc[s]) { csc[s] = csc[s]*fexp2(shc[s] - om) + os; shc[s] = om; }
                else             { csc[s] += os*fexp2(om - shc[s]); }
            }
        }
        // cross row-warp merge via smem
        if (rw == 0 && g == 0) {
            #pragma unroll
            for (int s = 0; s < 8; ++s) {
                int col = cw*32 + (s >> 1)*8 + 2*q + (s & 1);
                colm[col] = shc[s]; colsm[col] = csc[s];
            }
        }
        __syncthreads();
        if (rw == 1 && g == 0) {
            #pragma unroll
            for (int s = 0; s < 8; ++s) {
                int col = cw*32 + (s >> 1)*8 + 2*q + (s & 1);
                float mm = colm[col], ss = colsm[col];
                float M, S;
                if (mm > shc[s]) { M = mm; S = ss + csc[s]*fexp2(shc[s] - mm); }
                else             { M = shc[s]; S = csc[s] + ss*fexp2(mm - shc[s]); }
                g_c_m[rb*Nn + j0 + col] = M;
                g_c_s[rb*Nn + j0 + col] = S;
            }
        }
    }

    // ---- row merge: intra-warp (xor 1,2) then across 4 col-warps via smem ----
    float rss[8];
    #pragma unroll
    for (int s = 0; s < 8; ++s) { float2 f = asf2(rs2[s]); rss[s] = f.x + f.y; }
    #pragma unroll
    for (int mk = 1; mk <= 2; mk <<= 1) {
        #pragma unroll
        for (int s = 0; s < 8; ++s) {
            float om = __shfl_xor_sync(0xffffffffu, shift[s], mk);
            float os = __shfl_xor_sync(0xffffffffu, rss[s], mk);
            float ob = __shfl_xor_sync(0xffffffffu, bq[s], mk);
            int   oj = __shfl_xor_sync(0xffffffffu, bj[s], mk);
            if (om > shift[s]) { rss[s] = rss[s]*fexp2(shift[s] - om) + os; shift[s] = om; }
            else               { rss[s] += os*fexp2(om - shift[s]); }
            if (ob > bq[s] || (ob == bq[s] && oj < bj[s])) { bq[s] = ob; bj[s] = oj; }
        }
    }
    __syncthreads();
    if (q == 0) {
        #pragma unroll
        for (int s = 0; s < 8; ++s) {
            int row = (rw*4 + (s >> 1))*16 + (s & 1)*8 + g;
            rowm[row*4 + cw] = shift[s];
            rowss[row*4 + cw] = rss[s];
            rowb[row*4 + cw] = bq[s];
            rowj[row*4 + cw] = bj[s];
        }
    }
    __syncthreads();
    if (tid < 128) {
        float m = -3e38f, s = 0.f, bqv = -3e38f; int bjv = 0x7fffffff;
        #pragma unroll
        for (int c = 0; c < 4; ++c) {
            float mm = rowm[tid*4 + c], ss = rowss[tid*4 + c];
            if (mm > m) { s = s*fexp2(m - mm) + ss; m = mm; }
            else        { s += ss*fexp2(mm - m); }
            float bb = rowb[tid*4 + c]; int jj = rowj[tid*4 + c];
            if (bb > bqv || (bb == bqv && jj < bjv)) { bqv = bb; bjv = jj; }
        }
        g_r_m [cb*Nn + i0 + tid] = m;
        g_r_s [cb*Nn + i0 + tid] = s;
        g_r_bc[cb*Nn + i0 + tid] = bqv;
        g_r_bj[cb*Nn + i0 + tid] = bjv;
    }
}

// ---------------- k3 ----------------
__global__ void k3() {
    int i = blockIdx.x*blockDim.x + threadIdx.x;
    float m = -3e38f, s = 0.f, bqv = -3e38f; int bjv = 0x7fffffff;
    #pragma unroll
    for (int c = 0; c < NCB; ++c) {
        float mm = g_r_m[c*Nn + i], ss = g_r_s[c*Nn + i];
        if (mm > m) { s = s*fexp2(m - mm) + ss; m = mm; }
        else        { s += ss*fexp2(mm - m); }
        float bb = g_r_bc[c*Nn + i]; int jj = g_r_bj[c*Nn + i];
        if (bb > bqv || (bb == bqv && jj < bjv)) { bqv = bb; bjv = jj; }
    }
    g_lse1[i] = LN2*(m + log2f(s)) - logf((float)Nn);
    g_idx[i] = bjv;
    m = -3e38f; s = 0.f;
    #pragma unroll
    for (int r = 0; r < NRB; ++r) {
        float mm = g_c_m[r*Nn + i], ss = g_c_s[r*Nn + i];
        if (mm > m) { s = s*fexp2(m - mm) + ss; m = mm; }
        else        { s += ss*fexp2(mm - m); }
    }
    g_lse2[i] = LN2*(m + log2f(s));
}

// ---------------- k4 ----------------
__global__ void k4(float* __restrict__ out) {
    __shared__ double red[512];
    __shared__ int cnt[Nn];
    int tid = threadIdx.x;
    double s_lse1 = 0, s_phi1 = 0, s_lse2 = 0, s_phi2 = 0;
    for (int i = tid; i < Nn; i += 512) {
        s_lse1 += (double)g_lse1[i];
        s_phi1 += (double)g_phi1[i];
        s_lse2 += (double)g_lse2[i];
        s_phi2 += (double)g_phi2[i];
    }
    for (int i = tid; i < Nn; i += 512) cnt[i] = 0;
    __syncthreads();
    for (int i = tid; i < Nn; i += 512) atomicAdd(&cnt[g_idx[i]], 1);
    __syncthreads();
    double ent = 0;
    for (int i = tid; i < Nn; i += 512) {
        int c = cnt[i];
        if (c > 0) { float em = (float)c / (float)Nn; ent += (double)(em * logf(em + 1e-10f)); }
    }
    double vals[5] = {s_lse1, s_phi1, s_lse2, s_phi2, ent};
    for (int v = 0; v < 5; ++v) {
        red[tid] = vals[v]; __syncthreads();
        for (int s = 256; s > 0; s >>= 1) { if (tid < s) red[tid] += red[tid + s]; __syncthreads(); }
        vals[v] = red[0]; __syncthreads();
    }
    if (tid == 0) {
        double n = (double)Nn;
        double loss1 = (-0.1*vals[0] + vals[1]) / n;
        double loss2 = (-0.1*vals[2]) / n + 0.1*log(n) + vals[3]/n;
        out[2*OUTPLANE]     = (float)(0.25*(loss1 + loss2));
        out[2*OUTPLANE + 1] = (float)exp(-vals[4]);
    }
}

// ---------------- k5 ----------------
__global__ void k5(const float* __restrict__ z, const float* __restrict__ codebook,
                   float* __restrict__ out) {
    int o = blockIdx.x*256 + threadIdx.x;
    int w = o & 15, h = (o >> 4) & 15, c = (o >> 8) & 63, b = o >> 14;
    int i = (h*16 + w)*16 + b;
    out[o] = codebook[(g_idx[i] >> 3)*(2*Dd) + c];
    out[OUTPLANE + o] = z[o];
}

// ---------------- launch ----------------
extern "C" void kernel_launch(void* const* d_in, const int* in_sizes, int n_in,
                              void* d_out, int out_size) {
    const float* z        = (const float*)d_in[0];
    const float* codebook = (const float*)d_in[1];
    const float* w1       = (const float*)d_in[3];
    const float* b1       = (const float*)d_in[4];
    const float* w2       = (const float*)d_in[5];
    const float* b2       = (const float*)d_in[6];
    const float* noise    = (const float*)d_in[7];
    float* out = (float*)d_out;

    cudaFuncSetAttribute(k2, cudaFuncAttributeMaxDynamicSharedMemorySize, SMEM_BYTES);

    k0<<<1, 64>>>(w1, b1, w2, b2);
    {
        dim3 g(8, 32), bdim(32, 8);
        k_tr<<<g, bdim>>>(z);
    }
    k1<<<Nn/4, 128>>>(codebook, noise);
    {
        dim3 g(NRB, NCB);
        k2<<<g, 256, SMEM_BYTES>>>();
    }
    k3<<<Nn/256, 256>>>();
    k4<<<1, 512>>>(out);
    k5<<<OUTPLANE/256, 256>>>(z, codebook, out);
}

// round 6
// speedup vs baseline: 1.0442x; 1.0442x over previous
#include <cuda_runtime.h>
#include <math.h>
#include <stdint.h>

// ---------------- problem constants ----------------
#define Nn 4096
#define Dd 64
#define HKk 256
#define BM 128
#define BN 128
#define NRB 32
#define NCB 4
#define CHUNK 1024
#define TPC 8
#define OUTPLANE 262144
#define L2E10 14.426950408889634f   // 10 * log2(e)
#define LN2 0.6931471805599453f

typedef unsigned long long ull;

// ---------------- static device scratch ----------------
__device__ float g_zf[Nn*Dd];
__device__ float g_zf_hi[Nn*Dd], g_zf_lo[Nn*Dd];   // scaled by 2
__device__ float g_zs_hi[Nn*Dd], g_zs_lo[Nn*Dd];
__device__ float g_zf2[Nn], g_zs2[Nn], g_phi1[Nn], g_phi2[Nn];
__device__ float g_w1m[Dd], g_w2m[Dd], g_b1m, g_b2m;
__device__ unsigned g_aph1, g_aph2;
__device__ float g_r_m[NCB*Nn], g_r_s[NCB*Nn], g_r_bc[NCB*Nn];
__device__ int   g_r_bj[NCB*Nn];
__device__ float g_c_m[NRB*Nn], g_c_s[NRB*Nn];
__device__ int   g_idx[Nn];
__device__ float g_lse1[Nn], g_lse2[Nn];

// ---------------- f32x2 packed helpers ----------------
#define FMA2(d,a,b,c) asm("fma.rn.f32x2 %0, %1, %2, %3;" : "=l"(d) : "l"(a), "l"(b), "l"(c))
#define ADD2(d,a,b)   asm("add.rn.f32x2 %0, %1, %2;"     : "=l"(d) : "l"(a), "l"(b))
#define MUL2(d,a,b)   asm("mul.rn.f32x2 %0, %1, %2;"     : "=l"(d) : "l"(a), "l"(b))

__device__ __forceinline__ ull dup2(float x) {
    ull r; asm("mov.b64 %0, {%1, %1};" : "=l"(r) : "f"(x)); return r;
}
__device__ __forceinline__ ull pk2(float lo, float hi) {
    ull r; asm("mov.b64 %0, {%1, %2};" : "=l"(r) : "f"(lo), "f"(hi)); return r;
}
__device__ __forceinline__ float2 asf2(ull v) {
    float2 f; asm("mov.b64 {%0, %1}, %2;" : "=f"(f.x), "=f"(f.y) : "l"(v)); return f;
}

struct PC { ull MAG, NMAG, NEG1, C5, C4, C3, C2, C1, ONE, L2; };
__device__ __forceinline__ PC make_pc() {
    PC K;
    K.MAG  = dup2(12582912.0f);
    K.NMAG = dup2(-12582912.0f);
    K.NEG1 = dup2(-1.0f);
    K.C5   = dup2(0.00133335581f);
    K.C4   = dup2(0.00961812910f);
    K.C3   = dup2(0.0555041087f);
    K.C2   = dup2(0.240226507f);
    K.C1   = dup2(0.693147180f);
    K.ONE  = dup2(1.0f);
    K.L2   = dup2(L2E10);
    return K;
}

__device__ __forceinline__ void pexp2acc(ull &acc, ull t, const PC& K) {
    ull tb; ADD2(tb, t, K.MAG);
    ull rr; ADD2(rr, tb, K.NMAG);
    ull f;  FMA2(f, rr, K.NEG1, t);
    ull p = K.C5;
    FMA2(p, p, f, K.C4);
    FMA2(p, p, f, K.C3);
    FMA2(p, p, f, K.C2);
    FMA2(p, p, f, K.C1);
    FMA2(p, p, f, K.ONE);
    int elo = (int)(unsigned)tb         + (127 - 0x4B400000);
    int ehi = (int)(unsigned)(tb >> 32) + (127 - 0x4B400000);
    elo = elo < 0 ? 0 : elo;
    ehi = ehi < 0 ? 0 : ehi;
    ull sc = pk2(__int_as_float(elo << 23), __int_as_float(ehi << 23));
    FMA2(acc, p, sc, acc);
}

__device__ __forceinline__ float fexp2(float x) {
    float t  = fmaxf(x, -126.0f);
    float tb = t + 12582912.0f;
    int   ni = __float_as_int(tb);
    float r  = tb - 12582912.0f;
    float f  = t - r;
    float p  = 0.00133335581f;
    p = fmaf(p, f, 0.00961812910f);
    p = fmaf(p, f, 0.0555041087f);
    p = fmaf(p, f, 0.240226507f);
    p = fmaf(p, f, 0.693147180f);
    p = fmaf(p, f, 1.0f);
    float sc = __int_as_float((ni + (127 - 0x4B400000)) << 23);
    return p * sc;
}

__device__ __forceinline__ unsigned fenc(float f) {
    unsigned u = __float_as_uint(f);
    return (u & 0x80000000u) ? ~u : (u | 0x80000000u);
}
__device__ __forceinline__ float fdec(unsigned u) {
    return (u & 0x80000000u) ? __uint_as_float(u & 0x7fffffffu) : __uint_as_float(~u);
}

__device__ __forceinline__ float tf32_hi(float x) {
    uint32_t h; asm("cvt.rna.tf32.f32 %0, %1;" : "=r"(h) : "f"(x));
    return __uint_as_float(h);
}

// mma.sync m16n8k8 tf32 (sm_80+ baseline)
__device__ __forceinline__ void mma8(float* d, const uint4& a, const uint2& b) {
    asm("mma.sync.aligned.m16n8k8.row.col.f32.tf32.tf32.f32 "
        "{%0,%1,%2,%3}, {%4,%5,%6,%7}, {%8,%9}, {%0,%1,%2,%3};"
        : "+f"(d[0]), "+f"(d[1]), "+f"(d[2]), "+f"(d[3])
        : "r"(a.x), "r"(a.y), "r"(a.z), "r"(a.w), "r"(b.x), "r"(b.y));
}

// ---------------- smem layout (byte offsets from 1024-aligned base) ----------------
#define OFF_AHI 0
#define OFF_ALO 32768
#define OFF_BHI 65536
#define OFF_BLO 98304
#define OFF_NZF2 131072
#define OFF_LP2  131584
#define OFF_NZS2 132096
#define OFF_LP1  132608
#define OFF_COLM 133120        // 4 rw x 128 floats = 2048B
#define OFF_COLS 135168
#define OFF_ROWM 137216        // 128 rows x 4 cw = 2048B
#define OFF_ROWS 139264
#define OFF_ROWB 141312
#define OFF_ROWJ 143360
#define SMEM_BYTES (145408 + 1024)

// ---------------- k0 ----------------
__global__ void k0(const float* __restrict__ w1, const float* __restrict__ b1,
                   const float* __restrict__ w2, const float* __restrict__ b2) {
    int d = threadIdx.x;
    if (d < Dd) {
        float s1 = 0.f, s2 = 0.f;
        for (int k = 0; k < HKk; ++k) { s1 += w1[d*HKk + k]; s2 += w2[d*HKk + k]; }
        g_w1m[d] = s1 / (float)HKk;
        g_w2m[d] = s2 / (float)HKk;
    }
    if (d == 0) { float s = 0.f; for (int k = 0; k < HKk; ++k) s += b1[k]; g_b1m = s / (float)HKk; g_aph1 = 0u; }
    if (d == 1) { float s = 0.f; for (int k = 0; k < HKk; ++k) s += b2[k]; g_b2m = s / (float)HKk; g_aph2 = 0u; }
}

// ---------------- k_tr ----------------
__global__ void k_tr(const float* __restrict__ z) {
    __shared__ float t[32][33];
    int bx = blockIdx.x, by = blockIdx.y;
    int x = bx*32 + threadIdx.x;
    #pragma unroll
    for (int q = 0; q < 4; ++q) {
        int row = by*32 + threadIdx.y + q*8;
        t[threadIdx.y + q*8][threadIdx.x] = z[row*256 + x];
    }
    __syncthreads();
    #pragma unroll
    for (int q = 0; q < 4; ++q) {
        int col = bx*32 + threadIdx.y + q*8;
        int row = by*32 + threadIdx.x;
        g_zf[col*1024 + row] = t[threadIdx.x][threadIdx.y + q*8];
    }
}

// ---------------- k1 ----------------
__global__ void k1(const float* __restrict__ codebook, const float* __restrict__ noise) {
    int warp = threadIdx.x >> 5, lane = threadIdx.x & 31;
    int row = blockIdx.x*4 + warp;
    const float* crow = codebook + (row >> 3) * (2*Dd);
    const float* nrow = noise + row*Dd;
    const float* frow = g_zf + row*Dd;
    float zs2 = 0.f, p1 = 0.f, zf2 = 0.f, p2 = 0.f;
    #pragma unroll
    for (int q = 0; q < 2; ++q) {
        int d = lane + q*32;
        float mu  = crow[d];
        float cov = expf(crow[Dd + d]);
        float zs  = mu + cov * nrow[d];
        float zh = tf32_hi(zs);
        g_zs_hi[row*Dd + d] = zh;
        g_zs_lo[row*Dd + d] = tf32_hi(zs - zh);
        zs2 += zs*zs;
        p1  += zs * g_w1m[d];
        float zf = frow[d];
        float fh = tf32_hi(zf);
        g_zf_hi[row*Dd + d] = 2.0f * fh;
        g_zf_lo[row*Dd + d] = 2.0f * tf32_hi(zf - fh);
        zf2 += zf*zf;
        p2  += zf * g_w2m[d];
    }
    #pragma unroll
    for (int o = 16; o > 0; o >>= 1) {
        zs2 += __shfl_xor_sync(0xffffffffu, zs2, o);
        p1  += __shfl_xor_sync(0xffffffffu, p1,  o);
        zf2 += __shfl_xor_sync(0xffffffffu, zf2, o);
        p2  += __shfl_xor_sync(0xffffffffu, p2,  o);
    }
    if (lane == 0) {
        float phi1 = p1 + g_b1m, phi2 = p2 + g_b2m;
        g_zs2[row] = zs2;  g_phi1[row] = phi1;
        g_zf2[row] = zf2;  g_phi2[row] = phi2;
        atomicMax(&g_aph1, fenc(phi1));
        atomicMax(&g_aph2, fenc(phi2));
    }
}

// ---------------- k2: 512-thread mma.sync tf32x3 fused GEMM ----------------
__global__ void __launch_bounds__(512, 1) k2() {
    extern __shared__ char smem_raw[];
    char* sb = (char*)(((uintptr_t)smem_raw + 1023) & ~(uintptr_t)1023);

    const int tid  = threadIdx.x;
    const int lane = tid & 31, wid = tid >> 5;
    const int rw = wid >> 2, cw = wid & 3;     // warp row-quarter (0..3), col-quarter (0..3)
    const int q  = lane & 3,  g  = lane >> 2;  // thread-in-group, group
    const int rb = blockIdx.x, cb = blockIdx.y;
    const int i0 = rb * BM;
    const float S1g = L2E10 * fdec(g_aph1);
    const float S2g = L2E10 * fdec(g_aph2);
    const PC K = make_pc();

    float* nzf2s = (float*)(sb + OFF_NZF2);
    float* lp2s  = (float*)(sb + OFF_LP2);
    float* nzs2s = (float*)(sb + OFF_NZS2);
    float* lp1s  = (float*)(sb + OFF_LP1);
    float* colm  = (float*)(sb + OFF_COLM);
    float* colsm = (float*)(sb + OFF_COLS);
    float* rowm  = (float*)(sb + OFF_ROWM);
    float* rowss = (float*)(sb + OFF_ROWS);
    float* rowb  = (float*)(sb + OFF_ROWB);
    int*   rowj  = (int*)  (sb + OFF_ROWJ);

    // ---- stage A fragments (fragment-permuted, once) ----
    {
        float4* Ah = (float4*)(sb + OFF_AHI);
        float4* Al = (float4*)(sb + OFF_ALO);
        for (int t2 = tid; t2 < 2048; t2 += 512) {
            int kt = t2 >> 8, mt = (t2 >> 5) & 7, l = t2 & 31;
            int r0 = (i0 + mt*16 + (l >> 2)) * 64;
            int r8 = r0 + 8*64;
            int c0 = kt*8 + (l & 3);
            float4 v;
            v.x = g_zf_hi[r0 + c0];
            v.y = g_zf_hi[r8 + c0];
            v.z = g_zf_hi[r0 + c0 + 4];
            v.w = g_zf_hi[r8 + c0 + 4];
            Ah[t2] = v;
            v.x = g_zf_lo[r0 + c0];
            v.y = g_zf_lo[r8 + c0];
            v.z = g_zf_lo[r0 + c0 + 4];
            v.w = g_zf_lo[r8 + c0 + 4];
            Al[t2] = v;
        }
        if (tid < 128) {
            nzf2s[tid] = -g_zf2[i0 + tid];
            lp2s[tid]  = L2E10 * g_phi2[i0 + tid];
        }
    }
    __syncthreads();

    // hoisted row constants: slot s = m*2+h, row = (rw*2+m)*16 + h*8 + g
    float nzf2row[4], lp2row[4];
    #pragma unroll
    for (int m = 0; m < 2; ++m)
        #pragma unroll
        for (int h = 0; h < 2; ++h) {
            int row = (rw*2 + m)*16 + h*8 + g;
            nzf2row[m*2+h] = nzf2s[row];
            lp2row[m*2+h]  = lp2s[row];
        }

    // row state (4 slots)
    float bq[4], shift[4]; int bj[4]; ull rs2[4];
    #pragma unroll
    for (int s = 0; s < 4; ++s) { bq[s] = -3e38f; shift[s] = -1e30f; bj[s] = 0x7fffffff; rs2[s] = 0ull; }

    for (int t = 0; t < TPC; ++t) {
        const int j0 = cb*CHUNK + t*BN;

        __syncthreads();
        // ---- stage B fragments ----
        {
            float2* Bh = (float2*)(sb + OFF_BHI);
            float2* Bl = (float2*)(sb + OFF_BLO);
            for (int t2 = tid; t2 < 4096; t2 += 512) {
                int kt = t2 >> 9, nt = (t2 >> 5) & 15, l = t2 & 31;
                int n0 = (j0 + nt*8 + (l >> 2)) * 64;
                int ck = kt*8 + (l & 3);
                float2 v;
                v.x = g_zs_hi[n0 + ck];
                v.y = g_zs_hi[n0 + ck + 4];
                Bh[t2] = v;
                v.x = g_zs_lo[n0 + ck];
                v.y = g_zs_lo[n0 + ck + 4];
                Bl[t2] = v;
            }
            if (tid < 128) {
                nzs2s[tid] = -g_zs2[j0 + tid];
                lp1s[tid]  = L2E10 * g_phi1[j0 + tid];
            }
        }
        __syncthreads();

        // ---- GEMM: 3-split tf32 mma, 32x32 per warp ----
        float d[2][4][4];
        #pragma unroll
        for (int m = 0; m < 2; ++m)
            #pragma unroll
            for (int n = 0; n < 4; ++n)
                #pragma unroll
                for (int e = 0; e < 4; ++e) d[m][n][e] = 0.f;

        const uint4* Ah = (const uint4*)(sb + OFF_AHI);
        const uint4* Al = (const uint4*)(sb + OFF_ALO);
        const uint2* Bh = (const uint2*)(sb + OFF_BHI);
        const uint2* Bl = (const uint2*)(sb + OFF_BLO);

        #pragma unroll
        for (int kt = 0; kt < 8; ++kt) {
            uint4 ah[2], al[2];
            uint2 bh[4], bl[4];
            #pragma unroll
            for (int m = 0; m < 2; ++m) ah[m] = Ah[(kt*8 + rw*2 + m)*32 + lane];
            #pragma unroll
            for (int n = 0; n < 4; ++n) bh[n] = Bh[(kt*16 + cw*4 + n)*32 + lane];
            #pragma unroll
            for (int m = 0; m < 2; ++m)
                #pragma unroll
                for (int n = 0; n < 4; ++n) mma8(d[m][n], ah[m], bh[n]);
            #pragma unroll
            for (int m = 0; m < 2; ++m) al[m] = Al[(kt*8 + rw*2 + m)*32 + lane];
            #pragma unroll
            for (int m = 0; m < 2; ++m)
                #pragma unroll
                for (int n = 0; n < 4; ++n) mma8(d[m][n], al[m], bh[n]);
            #pragma unroll
            for (int n = 0; n < 4; ++n) bl[n] = Bl[(kt*16 + cw*4 + n)*32 + lane];
            #pragma unroll
            for (int m = 0; m < 2; ++m)
                #pragma unroll
                for (int n = 0; n < 4; ++n) mma8(d[m][n], ah[m], bl[n]);
        }

        // ---- c2 = D - zf2 - zs2 ----
        ull nzsp[4], lp1p[4];
        const int cbase = cw*32 + 2*q;
        #pragma unroll
        for (int n = 0; n < 4; ++n) {
            nzsp[n] = *(const ull*)(nzs2s + cbase + n*8);
            lp1p[n] = *(const ull*)(lp1s  + cbase + n*8);
        }
        #pragma unroll
        for (int m = 0; m < 2; ++m)
            #pragma unroll
            for (int h = 0; h < 2; ++h) {
                ull rowc = dup2(nzf2row[m*2+h]);
                #pragma unroll
                for (int n = 0; n < 4; ++n) {
                    ull x = pk2(d[m][n][2*h], d[m][n][2*h+1]);
                    ADD2(x, x, nzsp[n]);
                    ADD2(x, x, rowc);
                    float2 f = asf2(x);
                    d[m][n][2*h] = f.x; d[m][n][2*h+1] = f.y;
                }
            }

        // ---- row pass ----
        #pragma unroll
        for (int m = 0; m < 2; ++m)
            #pragma unroll
            for (int h = 0; h < 2; ++h) {
                const int s = m*2 + h;
                float bql = bq[s]; int bjl = bj[s];
                #pragma unroll
                for (int n = 0; n < 4; ++n) {
                    float fx = d[m][n][2*h], fy = d[m][n][2*h+1];
                    int jc = j0 + cw*32 + n*8 + 2*q;
                    if (fx > bql) { bql = fx; bjl = jc; }
                    if (fy > bql) { bql = fy; bjl = jc + 1; }
                }
                bq[s] = bql; bj[s] = bjl;
                float ns = fmaf(L2E10, bql, S1g);
                float rsc = fexp2(shift[s] - ns);
                shift[s] = ns;
                { ull rp = dup2(rsc); MUL2(rs2[s], rs2[s], rp); }
                ull msh = dup2(-ns);
                #pragma unroll
                for (int n = 0; n < 4; ++n) {
                    ull c2p = pk2(d[m][n][2*h], d[m][n][2*h+1]);
                    ull tt; ADD2(tt, lp1p[n], msh);
                    FMA2(tt, c2p, K.L2, tt);
                    pexp2acc(rs2[s], tt, K);
                }
            }

        // ---- col pass ----
        float cmA[4], cmB[4];
        #pragma unroll
        for (int n = 0; n < 4; ++n) { cmA[n] = -3e38f; cmB[n] = -3e38f; }
        #pragma unroll
        for (int m = 0; m < 2; ++m)
            #pragma unroll
            for (int h = 0; h < 2; ++h)
                #pragma unroll
                for (int n = 0; n < 4; ++n) {
                    cmA[n] = fmaxf(cmA[n], d[m][n][2*h]);
                    cmB[n] = fmaxf(cmB[n], d[m][n][2*h+1]);
                }
        float shA[4], shB[4]; ull nshp[4]; ull csp[4];
        #pragma unroll
        for (int n = 0; n < 4; ++n) {
            shA[n] = fmaf(L2E10, cmA[n], S2g);
            shB[n] = fmaf(L2E10, cmB[n], S2g);
            nshp[n] = pk2(-shA[n], -shB[n]);
            csp[n] = 0ull;
        }
        #pragma unroll
        for (int m = 0; m < 2; ++m)
            #pragma unroll
            for (int h = 0; h < 2; ++h) {
                ull lr = dup2(lp2row[m*2+h]);
                #pragma unroll
                for (int n = 0; n < 4; ++n) {
                    ull c2p = pk2(d[m][n][2*h], d[m][n][2*h+1]);
                    ull tt; ADD2(tt, lr, nshp[n]);
                    FMA2(tt, c2p, K.L2, tt);
                    pexp2acc(csp[n], tt, K);
                }
            }
        float shc[8], csc[8];
        #pragma unroll
        for (int n = 0; n < 4; ++n) {
            float2 f = asf2(csp[n]);
            shc[2*n] = shA[n];   csc[2*n] = f.x;
            shc[2*n+1] = shB[n]; csc[2*n+1] = f.y;
        }
        // intra-warp merge over g (xor 4,8,16)
        #pragma unroll
        for (int mk = 4; mk <= 16; mk <<= 1) {
            #pragma unroll
            for (int s = 0; s < 8; ++s) {
                float om = __shfl_xor_sync(0xffffffffu, shc[s], mk);
                float os = __shfl_xor_sync(0xffffffffu, csc[s], mk);
                if (om > shc[s]) { csc[s] = csc[s]*fexp2(shc[s] - om) + os; shc[s] = om; }
                else             { csc[s] += os*fexp2(om - shc[s]); }
            }
        }
        // cross rw merge: all 4 rw warps store, rw==0 merges
        if (g == 0) {
            #pragma unroll
            for (int s = 0; s < 8; ++s) {
                int col = cw*32 + (s >> 1)*8 + 2*q + (s & 1);
                colm[rw*128 + col] = shc[s]; colsm[rw*128 + col] = csc[s];
            }
        }
        __syncthreads();
        if (rw == 0 && g == 0) {
            #pragma unroll
            for (int s = 0; s < 8; ++s) {
                int col = cw*32 + (s >> 1)*8 + 2*q + (s & 1);
                float M = colm[col], S = colsm[col];
                #pragma unroll
                for (int r2 = 1; r2 < 4; ++r2) {
                    float mm = colm[r2*128 + col], ss = colsm[r2*128 + col];
                    if (mm > M) { S = S*fexp2(M - mm) + ss; M = mm; }
                    else        { S += ss*fexp2(mm - M); }
                }
                g_c_m[rb*Nn + j0 + col] = M;
                g_c_s[rb*Nn + j0 + col] = S;
            }
        }
    }

    // ---- row merge: intra-warp (xor 1,2) then across 4 col-warps via smem ----
    float rss[4];
    #pragma unroll
    for (int s = 0; s < 4; ++s) { float2 f = asf2(rs2[s]); rss[s] = f.x + f.y; }
    #pragma unroll
    for (int mk = 1; mk <= 2; mk <<= 1) {
        #pragma unroll
        for (int s = 0; s < 4; ++s) {
            float om = __shfl_xor_sync(0xffffffffu, shift[s], mk);
            float os = __shfl_xor_sync(0xffffffffu, rss[s], mk);
            float ob = __shfl_xor_sync(0xffffffffu, bq[s], mk);
            int   oj = __shfl_xor_sync(0xffffffffu, bj[s], mk);
            if (om > shift[s]) { rss[s] = rss[s]*fexp2(shift[s] - om) + os; shift[s] = om; }
            else               { rss[s] += os*fexp2(om - shift[s]); }
            if (ob > bq[s] || (ob == bq[s] && oj < bj[s])) { bq[s] = ob; bj[s] = oj; }
        }
    }
    __syncthreads();
    if (q == 0) {
        #pragma unroll
        for (int s = 0; s < 4; ++s) {
            int row = (rw*2 + (s >> 1))*16 + (s & 1)*8 + g;
            rowm[row*4 + cw] = shift[s];
            rowss[row*4 + cw] = rss[s];
            rowb[row*4 + cw] = bq[s];
            rowj[row*4 + cw] = bj[s];
        }
    }
    __syncthreads();
    if (tid < 128) {
        float m = -3e38f, s = 0.f, bqv = -3e38f; int bjv = 0x7fffffff;
        #pragma unroll
        for (int c = 0; c < 4; ++c) {
            float mm = rowm[tid*4 + c], ss = rowss[tid*4 + c];
            if (mm > m) { s = s*fexp2(m - mm) + ss; m = mm; }
            else        { s += ss*fexp2(mm - m); }
            float bb = rowb[tid*4 + c]; int jj = rowj[tid*4 + c];
            if (bb > bqv || (bb == bqv && jj < bjv)) { bqv = bb; bjv = jj; }
        }
        g_r_m [cb*Nn + i0 + tid] = m;
        g_r_s [cb*Nn + i0 + tid] = s;
        g_r_bc[cb*Nn + i0 + tid] = bqv;
        g_r_bj[cb*Nn + i0 + tid] = bjv;
    }
}

// ---------------- k3 ----------------
__global__ void k3() {
    int i = blockIdx.x*blockDim.x + threadIdx.x;
    float m = -3e38f, s = 0.f, bqv = -3e38f; int bjv = 0x7fffffff;
    #pragma unroll
    for (int c = 0; c < NCB; ++c) {
        float mm = g_r_m[c*Nn + i], ss = g_r_s[c*Nn + i];
        if (mm > m) { s = s*fexp2(m - mm) + ss; m = mm; }
        else        { s += ss*fexp2(mm - m); }
        float bb = g_r_bc[c*Nn + i]; int jj = g_r_bj[c*Nn + i];
        if (bb > bqv || (bb == bqv && jj < bjv)) { bqv = bb; bjv = jj; }
    }
    g_lse1[i] = LN2*(m + log2f(s)) - logf((float)Nn);
    g_idx[i] = bjv;
    m = -3e38f; s = 0.f;
    #pragma unroll
    for (int r = 0; r < NRB; ++r) {
        float mm = g_c_m[r*Nn + i], ss = g_c_s[r*Nn + i];
        if (mm > m) { s = s*fexp2(m - mm) + ss; m = mm; }
        else        { s += ss*fexp2(mm - m); }
    }
    g_lse2[i] = LN2*(m + log2f(s));
}

// ---------------- k4 ----------------
__global__ void k4(float* __restrict__ out) {
    __shared__ double red[512];
    __shared__ int cnt[Nn];
    int tid = threadIdx.x;
    double s_lse1 = 0, s_phi1 = 0, s_lse2 = 0, s_phi2 = 0;
    for (int i = tid; i < Nn; i += 512) {
        s_lse1 += (double)g_lse1[i];
        s_phi1 += (double)g_phi1[i];
        s_lse2 += (double)g_lse2[i];
        s_phi2 += (double)g_phi2[i];
    }
    for (int i = tid; i < Nn; i += 512) cnt[i] = 0;
    __syncthreads();
    for (int i = tid; i < Nn; i += 512) atomicAdd(&cnt[g_idx[i]], 1);
    __syncthreads();
    double ent = 0;
    for (int i = tid; i < Nn; i += 512) {
        int c = cnt[i];
        if (c > 0) { float em = (float)c / (float)Nn; ent += (double)(em * logf(em + 1e-10f)); }
    }
    double vals[5] = {s_lse1, s_phi1, s_lse2, s_phi2, ent};
    for (int v = 0; v < 5; ++v) {
        red[tid] = vals[v]; __syncthreads();
        for (int s = 256; s > 0; s >>= 1) { if (tid < s) red[tid] += red[tid + s]; __syncthreads(); }
        vals[v] = red[0]; __syncthreads();
    }
    if (tid == 0) {
        double n = (double)Nn;
        double loss1 = (-0.1*vals[0] + vals[1]) / n;
        double loss2 = (-0.1*vals[2]) / n + 0.1*log(n) + vals[3]/n;
        out[2*OUTPLANE]     = (float)(0.25*(loss1 + loss2));
        out[2*OUTPLANE + 1] = (float)exp(-vals[4]);
    }
}

// ---------------- k5 ----------------
__global__ void k5(const float* __restrict__ z, const float* __restrict__ codebook,
                   float* __restrict__ out) {
    int o = blockIdx.x*256 + threadIdx.x;
    int w = o & 15, h = (o >> 4) & 15, c = (o >> 8) & 63, b = o >> 14;
    int i = (h*16 + w)*16 + b;
    out[o] = codebook[(g_idx[i] >> 3)*(2*Dd) + c];
    out[OUTPLANE + o] = z[o];
}

// ---------------- launch ----------------
extern "C" void kernel_launch(void* const* d_in, const int* in_sizes, int n_in,
                              void* d_out, int out_size) {
    const float* z        = (const float*)d_in[0];
    const float* codebook = (const float*)d_in[1];
    const float* w1       = (const float*)d_in[3];
    const float* b1       = (const float*)d_in[4];
    const float* w2       = (const float*)d_in[5];
    const float* b2       = (const float*)d_in[6];
    const float* noise    = (const float*)d_in[7];
    float* out = (float*)d_out;

    cudaFuncSetAttribute(k2, cudaFuncAttributeMaxDynamicSharedMemorySize, SMEM_BYTES);

    k0<<<1, 64>>>(w1, b1, w2, b2);
    {
        dim3 g(8, 32), bdim(32, 8);
        k_tr<<<g, bdim>>>(z);
    }
    k1<<<Nn/4, 128>>>(codebook, noise);
    {
        dim3 g(NRB, NCB);
        k2<<<g, 512, SMEM_BYTES>>>();
    }
    k3<<<Nn/256, 256>>>();
    k4<<<1, 512>>>(out);
    k5<<<OUTPLANE/256, 256>>>(z, codebook, out);
}

// round 7
// speedup vs baseline: 1.2622x; 1.2088x over previous
#include <cuda_runtime.h>
#include <math.h>
#include <stdint.h>

// ---------------- problem constants ----------------
#define Nn 4096
#define Dd 64
#define HKk 256
#define BM 128
#define BN 128
#define NRB 32
#define NCB 4
#define CHUNK 1024
#define TPC 8
#define OUTPLANE 262144
#define L2E10 14.426950408889634f
#define LN2 0.6931471805599453f

typedef unsigned long long ull;

// ---------------- static device scratch ----------------
__device__ float g_zf[Nn*Dd];
__device__ float g_zf_hi[Nn*Dd], g_zf_lo[Nn*Dd];   // scaled by 2
__device__ float g_zs_hi[Nn*Dd], g_zs_lo[Nn*Dd];
__device__ float g_zf2[Nn], g_zs2[Nn], g_phi1[Nn], g_phi2[Nn];
__device__ float g_w1m[Dd], g_w2m[Dd], g_b1m, g_b2m;
__device__ unsigned g_aph1, g_aph2;
__device__ float g_r_m[NCB*Nn], g_r_s[NCB*Nn], g_r_bc[NCB*Nn];
__device__ int   g_r_bj[NCB*Nn];
__device__ float g_c_m[NRB*Nn], g_c_s[NRB*Nn];
__device__ int   g_idx[Nn];
__device__ float g_lse1[Nn], g_lse2[Nn];

// ---------------- f32x2 packed helpers ----------------
#define FMA2(d,a,b,c) asm("fma.rn.f32x2 %0, %1, %2, %3;" : "=l"(d) : "l"(a), "l"(b), "l"(c))
#define ADD2(d,a,b)   asm("add.rn.f32x2 %0, %1, %2;"     : "=l"(d) : "l"(a), "l"(b))
#define MUL2(d,a,b)   asm("mul.rn.f32x2 %0, %1, %2;"     : "=l"(d) : "l"(a), "l"(b))

__device__ __forceinline__ ull dup2(float x) {
    ull r; asm("mov.b64 %0, {%1, %1};" : "=l"(r) : "f"(x)); return r;
}
__device__ __forceinline__ ull pk2(float lo, float hi) {
    ull r; asm("mov.b64 %0, {%1, %2};" : "=l"(r) : "f"(lo), "f"(hi)); return r;
}
__device__ __forceinline__ float2 asf2(ull v) {
    float2 f; asm("mov.b64 {%0, %1}, %2;" : "=f"(f.x), "=f"(f.y) : "l"(v)); return f;
}

struct PC { ull MAG, NMAG, NEG1, C5, C4, C3, C2, C1, ONE, L2; };
__device__ __forceinline__ PC make_pc() {
    PC K;
    K.MAG  = dup2(12582912.0f);
    K.NMAG = dup2(-12582912.0f);
    K.NEG1 = dup2(-1.0f);
    K.C5   = dup2(0.00133335581f);
    K.C4   = dup2(0.00961812910f);
    K.C3   = dup2(0.0555041087f);
    K.C2   = dup2(0.240226507f);
    K.C1   = dup2(0.693147180f);
    K.ONE  = dup2(1.0f);
    K.L2   = dup2(L2E10);
    return K;
}

__device__ __forceinline__ void pexp2acc(ull &acc, ull t, const PC& K) {
    ull tb; ADD2(tb, t, K.MAG);
    ull rr; ADD2(rr, tb, K.NMAG);
    ull f;  FMA2(f, rr, K.NEG1, t);
    ull p = K.C5;
    FMA2(p, p, f, K.C4);
    FMA2(p, p, f, K.C3);
    FMA2(p, p, f, K.C2);
    FMA2(p, p, f, K.C1);
    FMA2(p, p, f, K.ONE);
    int elo = (int)(unsigned)tb         + (127 - 0x4B400000);
    int ehi = (int)(unsigned)(tb >> 32) + (127 - 0x4B400000);
    elo = elo < 0 ? 0 : elo;
    ehi = ehi < 0 ? 0 : ehi;
    ull sc = pk2(__int_as_float(elo << 23), __int_as_float(ehi << 23));
    FMA2(acc, p, sc, acc);
}

__device__ __forceinline__ float fexp2(float x) {
    float t  = fmaxf(x, -126.0f);
    float tb = t + 12582912.0f;
    int   ni = __float_as_int(tb);
    float r  = tb - 12582912.0f;
    float f  = t - r;
    float p  = 0.00133335581f;
    p = fmaf(p, f, 0.00961812910f);
    p = fmaf(p, f, 0.0555041087f);
    p = fmaf(p, f, 0.240226507f);
    p = fmaf(p, f, 0.693147180f);
    p = fmaf(p, f, 1.0f);
    float sc = __int_as_float((ni + (127 - 0x4B400000)) << 23);
    return p * sc;
}

__device__ __forceinline__ unsigned fenc(float f) {
    unsigned u = __float_as_uint(f);
    return (u & 0x80000000u) ? ~u : (u | 0x80000000u);
}
__device__ __forceinline__ float fdec(unsigned u) {
    return (u & 0x80000000u) ? __uint_as_float(u & 0x7fffffffu) : __uint_as_float(~u);
}

__device__ __forceinline__ float tf32_hi(float x) {
    uint32_t h; asm("cvt.rna.tf32.f32 %0, %1;" : "=r"(h) : "f"(x));
    return __uint_as_float(h);
}

// mma.sync m16n8k8 tf32 (sm_80+ baseline)
__device__ __forceinline__ void mma8(float* d, const uint4& a, const uint2& b) {
    asm("mma.sync.aligned.m16n8k8.row.col.f32.tf32.tf32.f32 "
        "{%0,%1,%2,%3}, {%4,%5,%6,%7}, {%8,%9}, {%0,%1,%2,%3};"
        : "+f"(d[0]), "+f"(d[1]), "+f"(d[2]), "+f"(d[3])
        : "r"(a.x), "r"(a.y), "r"(a.z), "r"(a.w), "r"(b.x), "r"(b.y));
}

// ---------------- cp.async ----------------
#define CPASYNC16(s, g) asm volatile("cp.async.cg.shared.global [%0], [%1], 16;" :: "r"(s), "l"(g))
#define CPASYNC4(s, g)  asm volatile("cp.async.ca.shared.global [%0], [%1], 4;"  :: "r"(s), "l"(g))
#define CP_COMMIT       asm volatile("cp.async.commit_group;" ::: "memory")
#define CP_WAIT(n)      asm volatile("cp.async.wait_group %0;" :: "n"(n) : "memory")

__device__ __forceinline__ uint32_t smem_u32(const void* p) {
    uint32_t a;
    asm("{ .reg .u64 t; cvta.to.shared.u64 t, %1; cvt.u32.u64 %0, t; }" : "=r"(a) : "l"(p));
    return a;
}

// ---------------- smem layout ----------------
// B natural layout: 128 rows x 68 floats (272B row stride, conflict-free lds)
#define BROW 272
#define OFF_AHI 0
#define OFF_ALO 32768
#define BBUF 69632
#define OFF_BHI(b) (65536 + (b)*BBUF)
#define OFF_BLO(b) (65536 + (b)*BBUF + 34816)
#define OFF_ZS2(b) (204800 + (b)*512)
#define OFF_P1(b)  (205824 + (b)*512)
#define OFF_NZF2 206848
#define OFF_P2   207360
#define OFF_COLM 207872
#define OFF_COLS 209920
#define OFF_ROWM 211968
#define OFF_ROWS 214016
#define OFF_ROWB 216064
#define OFF_ROWJ 218112
#define SMEM_BYTES (220160 + 1024)

// ---------------- k0 (parallel) ----------------
__global__ void k0(const float* __restrict__ w1, const float* __restrict__ b1,
                   const float* __restrict__ w2, const float* __restrict__ b2) {
    int tid = threadIdx.x;      // 256 threads
    int d = tid >> 2, part = tid & 3;
    float s1 = 0.f, s2 = 0.f;
    for (int k = part*64; k < part*64 + 64; ++k) {
        s1 += w1[d*HKk + k]; s2 += w2[d*HKk + k];
    }
    s1 += __shfl_xor_sync(0xffffffffu, s1, 1);
    s1 += __shfl_xor_sync(0xffffffffu, s1, 2);
    s2 += __shfl_xor_sync(0xffffffffu, s2, 1);
    s2 += __shfl_xor_sync(0xffffffffu, s2, 2);
    if (part == 0) { g_w1m[d] = s1 / (float)HKk; g_w2m[d] = s2 / (float)HKk; }
    if (tid < 64) {
        const float* bb = (tid < 32) ? b1 : b2;
        int l = tid & 31;
        float s = 0.f;
        for (int k = l; k < HKk; k += 32) s += bb[k];
        #pragma unroll
        for (int o = 16; o > 0; o >>= 1) s += __shfl_xor_sync(0xffffffffu, s, o);
        if (l == 0) {
            if (tid < 32) { g_b1m = s / (float)HKk; g_aph1 = 0u; }
            else          { g_b2m = s / (float)HKk; g_aph2 = 0u; }
        }
    }
}

// ---------------- k_tr ----------------
__global__ void k_tr(const float* __restrict__ z) {
    __shared__ float t[32][33];
    int bx = blockIdx.x, by = blockIdx.y;
    int x = bx*32 + threadIdx.x;
    #pragma unroll
    for (int q = 0; q < 4; ++q) {
        int row = by*32 + threadIdx.y + q*8;
        t[threadIdx.y + q*8][threadIdx.x] = z[row*256 + x];
    }
    __syncthreads();
    #pragma unroll
    for (int q = 0; q < 4; ++q) {
        int col = bx*32 + threadIdx.y + q*8;
        int row = by*32 + threadIdx.x;
        g_zf[col*1024 + row] = t[threadIdx.x][threadIdx.y + q*8];
    }
}

// ---------------- k1 ----------------
__global__ void k1(const float* __restrict__ codebook, const float* __restrict__ noise) {
    int warp = threadIdx.x >> 5, lane = threadIdx.x & 31;
    int row = blockIdx.x*4 + warp;
    const float* crow = codebook + (row >> 3) * (2*Dd);
    const float* nrow = noise + row*Dd;
    const float* frow = g_zf + row*Dd;
    float zs2 = 0.f, p1 = 0.f, zf2 = 0.f, p2 = 0.f;
    #pragma unroll
    for (int q = 0; q < 2; ++q) {
        int d = lane + q*32;
        float mu  = crow[d];
        float cov = expf(crow[Dd + d]);
        float zs  = mu + cov * nrow[d];
        float zh = tf32_hi(zs);
        g_zs_hi[row*Dd + d] = zh;
        g_zs_lo[row*Dd + d] = tf32_hi(zs - zh);
        zs2 += zs*zs;
        p1  += zs * g_w1m[d];
        float zf = frow[d];
        float fh = tf32_hi(zf);
        g_zf_hi[row*Dd + d] = 2.0f * fh;
        g_zf_lo[row*Dd + d] = 2.0f * tf32_hi(zf - fh);
        zf2 += zf*zf;
        p2  += zf * g_w2m[d];
    }
    #pragma unroll
    for (int o = 16; o > 0; o >>= 1) {
        zs2 += __shfl_xor_sync(0xffffffffu, zs2, o);
        p1  += __shfl_xor_sync(0xffffffffu, p1,  o);
        zf2 += __shfl_xor_sync(0xffffffffu, zf2, o);
        p2  += __shfl_xor_sync(0xffffffffu, p2,  o);
    }
    if (lane == 0) {
        float phi1 = p1 + g_b1m, phi2 = p2 + g_b2m;
        g_zs2[row] = zs2;  g_phi1[row] = phi1;
        g_zf2[row] = zf2;  g_phi2[row] = phi2;
        atomicMax(&g_aph1, fenc(phi1));
        atomicMax(&g_aph2, fenc(phi2));
    }
}

// ---------------- k2: cp.async double-buffered mma.sync tf32x3 ----------------
__global__ void __launch_bounds__(512, 1) k2() {
    extern __shared__ char smem_raw[];
    char* sb = (char*)(((uintptr_t)smem_raw + 1023) & ~(uintptr_t)1023);
    const uint32_t sba = smem_u32(sb);

    const int tid  = threadIdx.x;
    const int lane = tid & 31, wid = tid >> 5;
    const int rw = wid >> 2, cw = wid & 3;
    const int q  = lane & 3,  g  = lane >> 2;
    const int rb = blockIdx.x, cb = blockIdx.y;
    const int i0 = rb * BM;
    const float S1g = L2E10 * fdec(g_aph1);
    const float S2g = L2E10 * fdec(g_aph2);
    const PC K = make_pc();

    float* nzf2s = (float*)(sb + OFF_NZF2);
    float* p2s   = (float*)(sb + OFF_P2);
    float* colm  = (float*)(sb + OFF_COLM);
    float* colsm = (float*)(sb + OFF_COLS);
    float* rowm  = (float*)(sb + OFF_ROWM);
    float* rowss = (float*)(sb + OFF_ROWS);
    float* rowb  = (float*)(sb + OFF_ROWB);
    int*   rowj  = (int*)  (sb + OFF_ROWJ);

    // ---- stage B tile 0 via cp.async (buf 0) ----
    {
        const int j0 = cb*CHUNK;
        for (int idx = tid; idx < 2048; idx += 512) {
            int row = idx >> 4, ch = idx & 15;
            CPASYNC16(sba + OFF_BHI(0) + row*BROW + ch*16, g_zs_hi + (j0 + row)*64 + ch*4);
            CPASYNC16(sba + OFF_BLO(0) + row*BROW + ch*16, g_zs_lo + (j0 + row)*64 + ch*4);
        }
        if (tid < 128) {
            CPASYNC4(sba + OFF_ZS2(0) + tid*4, g_zs2 + j0 + tid);
            CPASYNC4(sba + OFF_P1(0)  + tid*4, g_phi1 + j0 + tid);
        }
        CP_COMMIT;
    }

    // ---- stage A fragments (fragment-permuted, once) + row scalars ----
    {
        float4* Ah = (float4*)(sb + OFF_AHI);
        float4* Al = (float4*)(sb + OFF_ALO);
        for (int t2 = tid; t2 < 2048; t2 += 512) {
            int kt = t2 >> 8, mt = (t2 >> 5) & 7, l = t2 & 31;
            int r0 = (i0 + mt*16 + (l >> 2)) * 64;
            int r8 = r0 + 8*64;
            int c0 = kt*8 + (l & 3);
            float4 v;
            v.x = g_zf_hi[r0 + c0];
            v.y = g_zf_hi[r8 + c0];
            v.z = g_zf_hi[r0 + c0 + 4];
            v.w = g_zf_hi[r8 + c0 + 4];
            Ah[t2] = v;
            v.x = g_zf_lo[r0 + c0];
            v.y = g_zf_lo[r8 + c0];
            v.z = g_zf_lo[r0 + c0 + 4];
            v.w = g_zf_lo[r8 + c0 + 4];
            Al[t2] = v;
        }
        if (tid < 128) {
            nzf2s[tid] = -g_zf2[i0 + tid];
            p2s[tid]   = g_phi2[i0 + tid];      // raw phi2
        }
    }
    __syncthreads();

    // hoisted row constants: slot s = m*2+h, row = (rw*2+m)*16 + h*8 + g
    float nzf2row[4], p2row[4];
    #pragma unroll
    for (int m = 0; m < 2; ++m)
        #pragma unroll
        for (int h = 0; h < 2; ++h) {
            int row = (rw*2 + m)*16 + h*8 + g;
            nzf2row[m*2+h] = nzf2s[row];
            p2row[m*2+h]   = p2s[row];
        }

    // row state (4 slots)
    float bq[4], shift[4]; int bj[4]; ull rs2[4];
    #pragma unroll
    for (int s = 0; s < 4; ++s) { bq[s] = -3e38f; shift[s] = -1e30f; bj[s] = 0x7fffffff; rs2[s] = 0ull; }

    const int browoff = (cw*32 + g)*BROW;

    for (int t = 0; t < TPC; ++t) {
        const int buf = t & 1;
        const int j0 = cb*CHUNK + t*BN;

        // prefetch next tile into other buffer
        if (t + 1 < TPC) {
            const int nb = (t + 1) & 1;
            const int nj0 = cb*CHUNK + (t + 1)*BN;
            for (int idx = tid; idx < 2048; idx += 512) {
                int row = idx >> 4, ch = idx & 15;
                CPASYNC16(sba + OFF_BHI(nb) + row*BROW + ch*16, g_zs_hi + (nj0 + row)*64 + ch*4);
                CPASYNC16(sba + OFF_BLO(nb) + row*BROW + ch*16, g_zs_lo + (nj0 + row)*64 + ch*4);
            }
            if (tid < 128) {
                CPASYNC4(sba + OFF_ZS2(nb) + tid*4, g_zs2 + nj0 + tid);
                CPASYNC4(sba + OFF_P1(nb)  + tid*4, g_phi1 + nj0 + tid);
            }
            CP_COMMIT;
            CP_WAIT(1);
        } else {
            CP_WAIT(0);
        }
        __syncthreads();

        // ---- GEMM: 3-split tf32 mma, 32x32 per warp ----
        float d[2][4][4];
        #pragma unroll
        for (int m = 0; m < 2; ++m)
            #pragma unroll
            for (int n = 0; n < 4; ++n)
                #pragma unroll
                for (int e = 0; e < 4; ++e) d[m][n][e] = 0.f;

        const uint4* Ah = (const uint4*)(sb + OFF_AHI);
        const uint4* Al = (const uint4*)(sb + OFF_ALO);
        const char* bhb = sb + OFF_BHI(buf) + browoff;
        const char* blb = sb + OFF_BLO(buf) + browoff;

        #pragma unroll
        for (int kt = 0; kt < 8; ++kt) {
            const int koff = kt*32 + q*4;
            uint4 ah[2], al[2];
            uint2 bh[4], bl[4];
            #pragma unroll
            for (int m = 0; m < 2; ++m) ah[m] = Ah[(kt*8 + rw*2 + m)*32 + lane];
            #pragma unroll
            for (int n = 0; n < 4; ++n) {
                bh[n].x = *(const uint32_t*)(bhb + n*2176 + koff);
                bh[n].y = *(const uint32_t*)(bhb + n*2176 + koff + 16);
            }
            #pragma unroll
            for (int m = 0; m < 2; ++m)
                #pragma unroll
                for (int n = 0; n < 4; ++n) mma8(d[m][n], ah[m], bh[n]);
            #pragma unroll
            for (int m = 0; m < 2; ++m) al[m] = Al[(kt*8 + rw*2 + m)*32 + lane];
            #pragma unroll
            for (int m = 0; m < 2; ++m)
                #pragma unroll
                for (int n = 0; n < 4; ++n) mma8(d[m][n], al[m], bh[n]);
            #pragma unroll
            for (int n = 0; n < 4; ++n) {
                bl[n].x = *(const uint32_t*)(blb + n*2176 + koff);
                bl[n].y = *(const uint32_t*)(blb + n*2176 + koff + 16);
            }
            #pragma unroll
            for (int m = 0; m < 2; ++m)
                #pragma unroll
                for (int n = 0; n < 4; ++n) mma8(d[m][n], ah[m], bl[n]);
        }

        // ---- c2 = D - zs2 - zf2 ----
        const float* zs2raw = (const float*)(sb + OFF_ZS2(buf));
        const float* p1raw  = (const float*)(sb + OFF_P1(buf));
        ull zsp[4], p1p[4];
        const int cbase = cw*32 + 2*q;
        #pragma unroll
        for (int n = 0; n < 4; ++n) {
            zsp[n] = (*(const ull*)(zs2raw + cbase + n*8)) ^ 0x8000000080000000ULL;
            p1p[n] = *(const ull*)(p1raw + cbase + n*8);
        }
        #pragma unroll
        for (int m = 0; m < 2; ++m)
            #pragma unroll
            for (int h = 0; h < 2; ++h) {
                ull rowc = dup2(nzf2row[m*2+h]);
                #pragma unroll
                for (int n = 0; n < 4; ++n) {
                    ull x = pk2(d[m][n][2*h], d[m][n][2*h+1]);
                    ADD2(x, x, zsp[n]);
                    ADD2(x, x, rowc);
                    float2 f = asf2(x);
                    d[m][n][2*h] = f.x; d[m][n][2*h+1] = f.y;
                }
            }

        // ---- row pass: argmax + shifted exp sums ----
        #pragma unroll
        for (int m = 0; m < 2; ++m)
            #pragma unroll
            for (int h = 0; h < 2; ++h) {
                const int s = m*2 + h;
                float bql = bq[s]; int bjl = bj[s];
                #pragma unroll
                for (int n = 0; n < 4; ++n) {
                    float fx = d[m][n][2*h], fy = d[m][n][2*h+1];
                    int jc = j0 + cw*32 + n*8 + 2*q;
                    if (fx > bql) { bql = fx; bjl = jc; }
                    if (fy > bql) { bql = fy; bjl = jc + 1; }
                }
                bq[s] = bql; bj[s] = bjl;
                float ns = fmaf(L2E10, bql, S1g);
                float rsc = fexp2(shift[s] - ns);
                shift[s] = ns;
                { ull rp = dup2(rsc); MUL2(rs2[s], rs2[s], rp); }
                ull msh = dup2(-ns);
                #pragma unroll
                for (int n = 0; n < 4; ++n) {
                    ull c2p = pk2(d[m][n][2*h], d[m][n][2*h+1]);
                    ull tp; ADD2(tp, c2p, p1p[n]);
                    ull tt; FMA2(tt, tp, K.L2, msh);
                    pexp2acc(rs2[s], tt, K);
                }
            }

        // ---- col pass ----
        float cmA[4], cmB[4];
        #pragma unroll
        for (int n = 0; n < 4; ++n) { cmA[n] = -3e38f; cmB[n] = -3e38f; }
        #pragma unroll
        for (int m = 0; m < 2; ++m)
            #pragma unroll
            for (int h = 0; h < 2; ++h)
                #pragma unroll
                for (int n = 0; n < 4; ++n) {
                    cmA[n] = fmaxf(cmA[n], d[m][n][2*h]);
                    cmB[n] = fmaxf(cmB[n], d[m][n][2*h+1]);
                }
        float shA[4], shB[4]; ull nshp[4]; ull csp[4];
        #pragma unroll
        for (int n = 0; n < 4; ++n) {
            shA[n] = fmaf(L2E10, cmA[n], S2g);
            shB[n] = fmaf(L2E10, cmB[n], S2g);
            nshp[n] = pk2(-shA[n], -shB[n]);
            csp[n] = 0ull;
        }
        #pragma unroll
        for (int m = 0; m < 2; ++m)
            #pragma unroll
            for (int h = 0; h < 2; ++h) {
                ull pr = dup2(p2row[m*2+h]);
                #pragma unroll
                for (int n = 0; n < 4; ++n) {
                    ull c2p = pk2(d[m][n][2*h], d[m][n][2*h+1]);
                    ull tp; ADD2(tp, c2p, pr);
                    ull tt; FMA2(tt, tp, K.L2, nshp[n]);
                    pexp2acc(csp[n], tt, K);
                }
            }
        float shc[8], csc[8];
        #pragma unroll
        for (int n = 0; n < 4; ++n) {
            float2 f = asf2(csp[n]);
            shc[2*n] = shA[n];   csc[2*n] = f.x;
            shc[2*n+1] = shB[n]; csc[2*n+1] = f.y;
        }
        #pragma unroll
        for (int mk = 4; mk <= 16; mk <<= 1) {
            #pragma unroll
            for (int s = 0; s < 8; ++s) {
                float om = __shfl_xor_sync(0xffffffffu, shc[s], mk);
                float os = __shfl_xor_sync(0xffffffffu, csc[s], mk);
                if (om > shc[s]) { csc[s] = csc[s]*fexp2(shc[s] - om) + os; shc[s] = om; }
                else             { csc[s] += os*fexp2(om - shc[s]); }
            }
        }
        if (g == 0) {
            #pragma unroll
            for (int s = 0; s < 8; ++s) {
                int col = cw*32 + (s >> 1)*8 + 2*q + (s & 1);
                colm[rw*128 + col] = shc[s]; colsm[rw*128 + col] = csc[s];
            }
        }
        __syncthreads();
        if (rw == 0 && g == 0) {
            #pragma unroll
            for (int s = 0; s < 8; ++s) {
                int col = cw*32 + (s >> 1)*8 + 2*q + (s & 1);
                float M = colm[col], S = colsm[col];
                #pragma unroll
                for (int r2 = 1; r2 < 4; ++r2) {
                    float mm = colm[r2*128 + col], ss = colsm[r2*128 + col];
                    if (mm > M) { S = S*fexp2(M - mm) + ss; M = mm; }
                    else        { S += ss*fexp2(mm - M); }
                }
                g_c_m[rb*Nn + j0 + col] = M;
                g_c_s[rb*Nn + j0 + col] = S;
            }
        }
    }

    // ---- row merge ----
    float rss[4];
    #pragma unroll
    for (int s = 0; s < 4; ++s) { float2 f = asf2(rs2[s]); rss[s] = f.x + f.y; }
    #pragma unroll
    for (int mk = 1; mk <= 2; mk <<= 1) {
        #pragma unroll
        for (int s = 0; s < 4; ++s) {
            float om = __shfl_xor_sync(0xffffffffu, shift[s], mk);
            float os = __shfl_xor_sync(0xffffffffu, rss[s], mk);
            float ob = __shfl_xor_sync(0xffffffffu, bq[s], mk);
            int   oj = __shfl_xor_sync(0xffffffffu, bj[s], mk);
            if (om > shift[s]) { rss[s] = rss[s]*fexp2(shift[s] - om) + os; shift[s] = om; }
            else               { rss[s] += os*fexp2(om - shift[s]); }
            if (ob > bq[s] || (ob == bq[s] && oj < bj[s])) { bq[s] = ob; bj[s] = oj; }
        }
    }
    __syncthreads();
    if (q == 0) {
        #pragma unroll
        for (int s = 0; s < 4; ++s) {
            int row = (rw*2 + (s >> 1))*16 + (s & 1)*8 + g;
            rowm[row*4 + cw] = shift[s];
            rowss[row*4 + cw] = rss[s];
            rowb[row*4 + cw] = bq[s];
            rowj[row*4 + cw] = bj[s];
        }
    }
    __syncthreads();
    if (tid < 128) {
        float m = -3e38f, s = 0.f, bqv = -3e38f; int bjv = 0x7fffffff;
        #pragma unroll
        for (int c = 0; c < 4; ++c) {
            float mm = rowm[tid*4 + c], ss = rowss[tid*4 + c];
            if (mm > m) { s = s*fexp2(m - mm) + ss; m = mm; }
            else        { s += ss*fexp2(mm - m); }
            float bb = rowb[tid*4 + c]; int jj = rowj[tid*4 + c];
            if (bb > bqv || (bb == bqv && jj < bjv)) { bqv = bb; bjv = jj; }
        }
        g_r_m [cb*Nn + i0 + tid] = m;
        g_r_s [cb*Nn + i0 + tid] = s;
        g_r_bc[cb*Nn + i0 + tid] = bqv;
        g_r_bj[cb*Nn + i0 + tid] = bjv;
    }
}

// ---------------- k3 ----------------
__global__ void k3() {
    int i = blockIdx.x*blockDim.x + threadIdx.x;
    float m = -3e38f, s = 0.f, bqv = -3e38f; int bjv = 0x7fffffff;
    #pragma unroll
    for (int c = 0; c < NCB; ++c) {
        float mm = g_r_m[c*Nn + i], ss = g_r_s[c*Nn + i];
        if (mm > m) { s = s*fexp2(m - mm) + ss; m = mm; }
        else        { s += ss*fexp2(mm - m); }
        float bb = g_r_bc[c*Nn + i]; int jj = g_r_bj[c*Nn + i];
        if (bb > bqv || (bb == bqv && jj < bjv)) { bqv = bb; bjv = jj; }
    }
    g_lse1[i] = LN2*(m + log2f(s)) - logf((float)Nn);
    g_idx[i] = bjv;
    m = -3e38f; s = 0.f;
    #pragma unroll
    for (int r = 0; r < NRB; ++r) {
        float mm = g_c_m[r*Nn + i], ss = g_c_s[r*Nn + i];
        if (mm > m) { s = s*fexp2(m - mm) + ss; m = mm; }
        else        { s += ss*fexp2(mm - m); }
    }
    g_lse2[i] = LN2*(m + log2f(s));
}

// ---------------- k4 (1024 threads, warp-shuffle reduction) ----------------
__global__ void k4(float* __restrict__ out) {
    __shared__ int cnt[Nn];
    __shared__ double wred[32*5];
    int tid = threadIdx.x;
    double v0 = 0, v1 = 0, v2 = 0, v3 = 0;
    for (int i = tid; i < Nn; i += 1024) {
        v0 += (double)g_lse1[i];
        v1 += (double)g_phi1[i];
        v2 += (double)g_lse2[i];
        v3 += (double)g_phi2[i];
    }
    for (int i = tid; i < Nn; i += 1024) cnt[i] = 0;
    __syncthreads();
    for (int i = tid; i < Nn; i += 1024) atomicAdd(&cnt[g_idx[i]], 1);
    __syncthreads();
    double v4 = 0;
    for (int i = tid; i < Nn; i += 1024) {
        int c = cnt[i];
        if (c > 0) { float em = (float)c / (float)Nn; v4 += (double)(em * logf(em + 1e-10f)); }
    }
    double vals[5] = {v0, v1, v2, v3, v4};
    int lane = tid & 31, warp = tid >> 5;
    #pragma unroll
    for (int v = 0; v < 5; ++v) {
        double x = vals[v];
        #pragma unroll
        for (int o = 16; o > 0; o >>= 1) x += __shfl_xor_sync(0xffffffffu, x, o);
        if (lane == 0) wred[warp*5 + v] = x;
    }
    __syncthreads();
    if (tid == 0) {
        double t[5] = {0, 0, 0, 0, 0};
        for (int w = 0; w < 32; ++w)
            for (int v = 0; v < 5; ++v) t[v] += wred[w*5 + v];
        double n = (double)Nn;
        double loss1 = (-0.1*t[0] + t[1]) / n;
        double loss2 = (-0.1*t[2]) / n + 0.1*log(n) + t[3]/n;
        out[2*OUTPLANE]     = (float)(0.25*(loss1 + loss2));
        out[2*OUTPLANE + 1] = (float)exp(-t[4]);
    }
}

// ---------------- k5 ----------------
__global__ void k5(const float* __restrict__ z, const float* __restrict__ codebook,
                   float* __restrict__ out) {
    int o = blockIdx.x*256 + threadIdx.x;
    int w = o & 15, h = (o >> 4) & 15, c = (o >> 8) & 63, b = o >> 14;
    int i = (h*16 + w)*16 + b;
    out[o] = codebook[(g_idx[i] >> 3)*(2*Dd) + c];
    out[OUTPLANE + o] = z[o];
}

// ---------------- launch ----------------
extern "C" void kernel_launch(void* const* d_in, const int* in_sizes, int n_in,
                              void* d_out, int out_size) {
    const float* z        = (const float*)d_in[0];
    const float* codebook = (const float*)d_in[1];
    const float* w1       = (const float*)d_in[3];
    const float* b1       = (const float*)d_in[4];
    const float* w2       = (const float*)d_in[5];
    const float* b2       = (const float*)d_in[6];
    const float* noise    = (const float*)d_in[7];
    float* out = (float*)d_out;

    cudaFuncSetAttribute(k2, cudaFuncAttributeMaxDynamicSharedMemorySize, SMEM_BYTES);

    k0<<<1, 256>>>(w1, b1, w2, b2);
    {
        dim3 g(8, 32), bdim(32, 8);
        k_tr<<<g, bdim>>>(z);
    }
    k1<<<Nn/4, 128>>>(codebook, noise);
    {
        dim3 g(NRB, NCB);
        k2<<<g, 512, SMEM_BYTES>>>();
    }
    k3<<<Nn/256, 256>>>();
    k4<<<1, 1024>>>(out);
    k5<<<OUTPLANE/256, 256>>>(z, codebook, out);
}

// round 8
// speedup vs baseline: 1.4101x; 1.1172x over previous
#include <cuda_runtime.h>
#include <math.h>
#include <stdint.h>

// ---------------- problem constants ----------------
#define Nn 4096
#define Dd 64
#define HKk 256
#define BM 128
#define BN 128
#define NRB 32
#define NCB 4
#define CHUNK 1024
#define TPC 8
#define OUTPLANE 262144
#define L2E10 14.426950408889634f
#define LN2 0.6931471805599453f

typedef unsigned long long ull;

// ---------------- static device scratch ----------------
__device__ float g_zf[Nn*Dd];
__device__ float g_zf_hi[Nn*Dd], g_zf_lo[Nn*Dd];   // scaled by 2 (A side)
__device__ float g_zsP[Nn*128];                    // B side: [row][hi 64 perm | lo 64 perm]
__device__ float g_zf2[Nn], g_zs2[Nn], g_phi1[Nn], g_phi2[Nn];
__device__ float g_w1m[Dd], g_w2m[Dd], g_b1m, g_b2m;
__device__ unsigned g_aph1, g_aph2;
__device__ float g_r_m[NCB*Nn], g_r_s[NCB*Nn], g_r_bc[NCB*Nn];
__device__ int   g_r_bj[NCB*Nn];
__device__ float g_c_m[NRB*Nn], g_c_s[NRB*Nn];
__device__ int   g_idx[Nn];
__device__ float g_lse1[Nn], g_lse2[Nn];

// ---------------- f32x2 packed helpers ----------------
#define FMA2(d,a,b,c) asm("fma.rn.f32x2 %0, %1, %2, %3;" : "=l"(d) : "l"(a), "l"(b), "l"(c))
#define ADD2(d,a,b)   asm("add.rn.f32x2 %0, %1, %2;"     : "=l"(d) : "l"(a), "l"(b))
#define MUL2(d,a,b)   asm("mul.rn.f32x2 %0, %1, %2;"     : "=l"(d) : "l"(a), "l"(b))

__device__ __forceinline__ ull dup2(float x) {
    ull r; asm("mov.b64 %0, {%1, %1};" : "=l"(r) : "f"(x)); return r;
}
__device__ __forceinline__ ull pk2(float lo, float hi) {
    ull r; asm("mov.b64 %0, {%1, %2};" : "=l"(r) : "f"(lo), "f"(hi)); return r;
}
__device__ __forceinline__ float2 asf2(ull v) {
    float2 f; asm("mov.b64 {%0, %1}, %2;" : "=f"(f.x), "=f"(f.y) : "l"(v)); return f;
}

struct PC { ull MAG, NMAG, NEG1, D3, D2, D1, ONE, L2; };
__device__ __forceinline__ PC make_pc() {
    PC K;
    K.MAG  = dup2(12582912.0f);
    K.NMAG = dup2(-12582912.0f);
    K.NEG1 = dup2(-1.0f);
    K.D3   = dup2(0.0558367f);
    K.D2   = dup2(0.2414282f);
    K.D1   = dup2(0.6931472f);
    K.ONE  = dup2(1.0f);
    K.L2   = dup2(L2E10);
    return K;
}

// acc += exp2(t) (deg-3, rel err ~1e-4; args <= 0, underflow clamps to 0)
__device__ __forceinline__ void pexp2acc(ull &acc, ull t, const PC& K) {
    ull tb; ADD2(tb, t, K.MAG);
    ull rr; ADD2(rr, tb, K.NMAG);
    ull f;  FMA2(f, rr, K.NEG1, t);
    ull p = K.D3;
    FMA2(p, p, f, K.D2);
    FMA2(p, p, f, K.D1);
    FMA2(p, p, f, K.ONE);
    int elo = (int)(unsigned)tb         + (127 - 0x4B400000);
    int ehi = (int)(unsigned)(tb >> 32) + (127 - 0x4B400000);
    elo = elo < 0 ? 0 : elo;
    ehi = ehi < 0 ? 0 : ehi;
    ull sc = pk2(__int_as_float(elo << 23), __int_as_float(ehi << 23));
    FMA2(acc, p, sc, acc);
}

// scalar exp2 (deg-5, merges only)
__device__ __forceinline__ float fexp2(float x) {
    float t  = fmaxf(x, -126.0f);
    float tb = t + 12582912.0f;
    int   ni = __float_as_int(tb);
    float r  = tb - 12582912.0f;
    float f  = t - r;
    float p  = 0.00133335581f;
    p = fmaf(p, f, 0.00961812910f);
    p = fmaf(p, f, 0.0555041087f);
    p = fmaf(p, f, 0.240226507f);
    p = fmaf(p, f, 0.693147180f);
    p = fmaf(p, f, 1.0f);
    float sc = __int_as_float((ni + (127 - 0x4B400000)) << 23);
    return p * sc;
}

__device__ __forceinline__ unsigned fenc(float f) {
    unsigned u = __float_as_uint(f);
    return (u & 0x80000000u) ? ~u : (u | 0x80000000u);
}
__device__ __forceinline__ float fdec(unsigned u) {
    return (u & 0x80000000u) ? __uint_as_float(u & 0x7fffffffu) : __uint_as_float(~u);
}

__device__ __forceinline__ float tf32_hi(float x) {
    uint32_t h; asm("cvt.rna.tf32.f32 %0, %1;" : "=r"(h) : "f"(x));
    return __uint_as_float(h);
}

// mma.sync m16n8k8 tf32
__device__ __forceinline__ void mma8(float* d, const uint4& a, const uint2& b) {
    asm("mma.sync.aligned.m16n8k8.row.col.f32.tf32.tf32.f32 "
        "{%0,%1,%2,%3}, {%4,%5,%6,%7}, {%8,%9}, {%0,%1,%2,%3};"
        : "+f"(d[0]), "+f"(d[1]), "+f"(d[2]), "+f"(d[3])
        : "r"(a.x), "r"(a.y), "r"(a.z), "r"(a.w), "r"(b.x), "r"(b.y));
}

// ---------------- cp.async ----------------
#define CPASYNC16(s, g) asm volatile("cp.async.cg.shared.global [%0], [%1], 16;" :: "r"(s), "l"(g))
#define CPASYNC4(s, g)  asm volatile("cp.async.ca.shared.global [%0], [%1], 4;"  :: "r"(s), "l"(g))
#define CP_COMMIT       asm volatile("cp.async.commit_group;" ::: "memory")
#define CP_WAIT(n)      asm volatile("cp.async.wait_group %0;" :: "n"(n) : "memory")

__device__ __forceinline__ uint32_t smem_u32(const void* p) {
    uint32_t a;
    asm("{ .reg .u64 t; cvta.to.shared.u64 t, %1; cvt.u32.u64 %0, t; }" : "=r"(a) : "l"(p));
    return a;
}

// ---------------- smem layout (bytes) ----------------
// B row: 544B = [hi 64 perm floats | lo 64 perm floats | pad 8]; 136 % 32 == 8 -> conflict-free LDS.64
#define BROW 544
#define BBUF (128*BROW)            // 69632
#define OFF_A    0                 // AHI 32768 + ALO 32768
#define OFF_ALO  32768
#define OFF_B    65536             // 2 bufs x 69632 = 139264 -> ends 204800
#define OFF_ZS2(b) (204800 + (b)*512)
#define OFF_P1(b)  (205824 + (b)*512)
#define OFF_NZF2 206848
#define OFF_P2   207360
#define OFF_COLM 207872            // 2 bufs x 4rw x 128 x 4B = 4096
#define OFF_COLS 211968            // 4096
#define OFF_ROWM 216064            // 2048 each
#define OFF_ROWS 218112
#define OFF_ROWB 220160
#define OFF_ROWJ 222208
#define SMEM_BYTES (224256 + 1024)

// ---------------- k0tr: fused w/b means (block 256) + transpose (blocks 0..255) ----------------
__global__ void k0tr(const float* __restrict__ z,
                     const float* __restrict__ w1, const float* __restrict__ b1,
                     const float* __restrict__ w2, const float* __restrict__ b2) {
    __shared__ float tsh[32][33];
    int tid = threadIdx.x;
    int blk = blockIdx.x;
    if (blk == 256) {
        int d = tid >> 2, part = tid & 3;
        float s1 = 0.f, s2 = 0.f;
        for (int k = part*64; k < part*64 + 64; ++k) {
            s1 += w1[d*HKk + k]; s2 += w2[d*HKk + k];
        }
        s1 += __shfl_xor_sync(0xffffffffu, s1, 1);
        s1 += __shfl_xor_sync(0xffffffffu, s1, 2);
        s2 += __shfl_xor_sync(0xffffffffu, s2, 1);
        s2 += __shfl_xor_sync(0xffffffffu, s2, 2);
        if (part == 0) { g_w1m[d] = s1 / (float)HKk; g_w2m[d] = s2 / (float)HKk; }
        if (tid < 64) {
            const float* bb = (tid < 32) ? b1 : b2;
            int l = tid & 31;
            float s = 0.f;
            for (int k = l; k < HKk; k += 32) s += bb[k];
            #pragma unroll
            for (int o = 16; o > 0; o >>= 1) s += __shfl_xor_sync(0xffffffffu, s, o);
            if (l == 0) {
                if (tid < 32) { g_b1m = s / (float)HKk; g_aph1 = 0u; }
                else          { g_b2m = s / (float)HKk; g_aph2 = 0u; }
            }
        }
        return;
    }
    int bx = blk & 7, by = blk >> 3;
    int tx = tid & 31, ty = tid >> 5;    // ty 0..7
    int x = bx*32 + tx;
    #pragma unroll
    for (int q = 0; q < 4; ++q) {
        int row = by*32 + ty + q*8;
        tsh[ty + q*8][tx] = z[row*256 + x];
    }
    __syncthreads();
    #pragma unroll
    for (int q = 0; q < 4; ++q) {
        int col = bx*32 + ty + q*8;
        int row = by*32 + tx;
        g_zf[col*1024 + row] = tsh[tx][ty + q*8];
    }
}

// ---------------- k1: zs, splits, norms, phi; B side pre-permuted ----------------
__global__ void k1(const float* __restrict__ codebook, const float* __restrict__ noise) {
    int warp = threadIdx.x >> 5, lane = threadIdx.x & 31;
    int row = blockIdx.x*4 + warp;
    const float* crow = codebook + (row >> 3) * (2*Dd);
    const float* nrow = noise + row*Dd;
    const float* frow = g_zf + row*Dd;
    float zs2 = 0.f, p1 = 0.f, zf2 = 0.f, p2 = 0.f;
    #pragma unroll
    for (int q = 0; q < 2; ++q) {
        int d = lane + q*32;
        float mu  = crow[d];
        float cov = expf(crow[Dd + d]);
        float zs  = mu + cov * nrow[d];
        float zh = tf32_hi(zs);
        // paired-permuted B layout: pos = kt*8 + (d&3)*2 + ((d>>2)&1)
        int pos = ((d >> 3) << 3) + ((d & 3) << 1) + ((d >> 2) & 1);
        g_zsP[row*128 + pos]      = zh;
        g_zsP[row*128 + 64 + pos] = tf32_hi(zs - zh);
        zs2 += zs*zs;
        p1  += zs * g_w1m[d];
        float zf = frow[d];
        float fh = tf32_hi(zf);
        g_zf_hi[row*Dd + d] = 2.0f * fh;
        g_zf_lo[row*Dd + d] = 2.0f * tf32_hi(zf - fh);
        zf2 += zf*zf;
        p2  += zf * g_w2m[d];
    }
    #pragma unroll
    for (int o = 16; o > 0; o >>= 1) {
        zs2 += __shfl_xor_sync(0xffffffffu, zs2, o);
        p1  += __shfl_xor_sync(0xffffffffu, p1,  o);
        zf2 += __shfl_xor_sync(0xffffffffu, zf2, o);
        p2  += __shfl_xor_sync(0xffffffffu, p2,  o);
    }
    if (lane == 0) {
        float phi1 = p1 + g_b1m, phi2 = p2 + g_b2m;
        g_zs2[row] = zs2;  g_phi1[row] = phi1;
        g_zf2[row] = zf2;  g_phi2[row] = phi2;
        atomicMax(&g_aph1, fenc(phi1));
        atomicMax(&g_aph2, fenc(phi2));
    }
}

// ---------------- k2 ----------------
__global__ void __launch_bounds__(512, 1) k2() {
    extern __shared__ char smem_raw[];
    char* sb = (char*)(((uintptr_t)smem_raw + 1023) & ~(uintptr_t)1023);
    const uint32_t sba = smem_u32(sb);

    const int tid  = threadIdx.x;
    const int lane = tid & 31, wid = tid >> 5;
    const int rw = wid >> 2, cw = wid & 3;
    const int q  = lane & 3,  g  = lane >> 2;
    const int rb = blockIdx.x, cb = blockIdx.y;
    const int i0 = rb * BM;
    const float S1g = L2E10 * fdec(g_aph1);
    const float S2g = L2E10 * fdec(g_aph2);
    const PC K = make_pc();

    float* nzf2s = (float*)(sb + OFF_NZF2);
    float* p2s   = (float*)(sb + OFF_P2);
    float* colm  = (float*)(sb + OFF_COLM);
    float* colsm = (float*)(sb + OFF_COLS);
    float* rowm  = (float*)(sb + OFF_ROWM);
    float* rowss = (float*)(sb + OFF_ROWS);
    float* rowb  = (float*)(sb + OFF_ROWB);
    int*   rowj  = (int*)  (sb + OFF_ROWJ);

    // ---- stage B tile 0 (buf 0) ----
    {
        const int j0 = cb*CHUNK;
        for (int idx = tid; idx < 4096; idx += 512) {
            int row = idx >> 5, ch = idx & 31;
            CPASYNC16(sba + OFF_B + row*BROW + ch*16, g_zsP + (j0 + row)*128 + ch*4);
        }
        if (tid < 128) {
            CPASYNC4(sba + OFF_ZS2(0) + tid*4, g_zs2 + j0 + tid);
            CPASYNC4(sba + OFF_P1(0)  + tid*4, g_phi1 + j0 + tid);
        }
        CP_COMMIT;
    }

    // ---- stage A fragments + row scalars ----
    {
        float4* Ah = (float4*)(sb + OFF_A);
        float4* Al = (float4*)(sb + OFF_ALO);
        for (int t2 = tid; t2 < 2048; t2 += 512) {
            int kt = t2 >> 8, mt = (t2 >> 5) & 7, l = t2 & 31;
            int r0 = (i0 + mt*16 + (l >> 2)) * 64;
            int r8 = r0 + 8*64;
            int c0 = kt*8 + (l & 3);
            float4 v;
            v.x = g_zf_hi[r0 + c0];
            v.y = g_zf_hi[r8 + c0];
            v.z = g_zf_hi[r0 + c0 + 4];
            v.w = g_zf_hi[r8 + c0 + 4];
            Ah[t2] = v;
            v.x = g_zf_lo[r0 + c0];
            v.y = g_zf_lo[r8 + c0];
            v.z = g_zf_lo[r0 + c0 + 4];
            v.w = g_zf_lo[r8 + c0 + 4];
            Al[t2] = v;
        }
        if (tid < 128) {
            nzf2s[tid] = -g_zf2[i0 + tid];
            p2s[tid]   = g_phi2[i0 + tid];
        }
    }
    __syncthreads();

    float nzf2row[4], p2row[4];
    #pragma unroll
    for (int m = 0; m < 2; ++m)
        #pragma unroll
        for (int h = 0; h < 2; ++h) {
            int row = (rw*2 + m)*16 + h*8 + g;
            nzf2row[m*2+h] = nzf2s[row];
            p2row[m*2+h]   = p2s[row];
        }

    float bq[4], shift[4]; int bj[4]; ull rs2[4];
    #pragma unroll
    for (int s = 0; s < 4; ++s) { bq[s] = -3e38f; shift[s] = -1e30f; bj[s] = 0x7fffffff; rs2[s] = 0ull; }

    const char* bthread = sb + OFF_B + (cw*32 + g)*BROW;   // + buf*BBUF*... applied per tile

    for (int t = 0; t < TPC; ++t) {
        const int buf = t & 1;
        const int j0 = cb*CHUNK + t*BN;

        // prefetch next tile
        if (t + 1 < TPC) {
            const int nb = (t + 1) & 1;
            const int nj0 = cb*CHUNK + (t + 1)*BN;
            for (int idx = tid; idx < 4096; idx += 512) {
                int row = idx >> 5, ch = idx & 31;
                CPASYNC16(sba + OFF_B + nb*BBUF + row*BROW + ch*16, g_zsP + (nj0 + row)*128 + ch*4);
            }
            if (tid < 128) {
                CPASYNC4(sba + OFF_ZS2(nb) + tid*4, g_zs2 + nj0 + tid);
                CPASYNC4(sba + OFF_P1(nb)  + tid*4, g_phi1 + nj0 + tid);
            }
            CP_COMMIT;
            CP_WAIT(1);
        } else {
            CP_WAIT(0);
        }
        __syncthreads();

        // ---- staggered merge of previous tile's col partials (warps 0-3, lanes g==0) ----
        if (t > 0 && rw == 0 && g == 0) {
            const int pv = (t - 1) & 1;
            const int pj0 = cb*CHUNK + (t - 1)*BN;
            const float* cmm = colm + pv*512;
            const float* css = colsm + pv*512;
            #pragma unroll
            for (int s = 0; s < 8; ++s) {
                int col = cw*32 + (s >> 1)*8 + 2*q + (s & 1);
                float M = cmm[col], S = css[col];
                #pragma unroll
                for (int r2 = 1; r2 < 4; ++r2) {
                    float mm = cmm[r2*128 + col], ss = css[r2*128 + col];
                    if (mm > M) { S = S*fexp2(M - mm) + ss; M = mm; }
                    else        { S += ss*fexp2(mm - M); }
                }
                g_c_m[rb*Nn + pj0 + col] = M;
                g_c_s[rb*Nn + pj0 + col] = S;
            }
        }

        // ---- GEMM: 3-split tf32 mma ----
        float d[2][4][4];
        #pragma unroll
        for (int m = 0; m < 2; ++m)
            #pragma unroll
            for (int n = 0; n < 4; ++n)
                #pragma unroll
                for (int e = 0; e < 4; ++e) d[m][n][e] = 0.f;

        const uint4* Ah = (const uint4*)(sb + OFF_A);
        const uint4* Al = (const uint4*)(sb + OFF_ALO);
        const char* bb = bthread + buf*BBUF;

        #pragma unroll
        for (int kt = 0; kt < 8; ++kt) {
            const int koff = kt*32 + q*8;
            uint4 ah[2], al[2];
            uint2 bh[4], bl[4];
            #pragma unroll
            for (int m = 0; m < 2; ++m) ah[m] = Ah[(kt*8 + rw*2 + m)*32 + lane];
            #pragma unroll
            for (int n = 0; n < 4; ++n) bh[n] = *(const uint2*)(bb + n*(8*BROW) + koff);
            #pragma unroll
            for (int m = 0; m < 2; ++m)
                #pragma unroll
                for (int n = 0; n < 4; ++n) mma8(d[m][n], ah[m], bh[n]);
            #pragma unroll
            for (int m = 0; m < 2; ++m) al[m] = Al[(kt*8 + rw*2 + m)*32 + lane];
            #pragma unroll
            for (int m = 0; m < 2; ++m)
                #pragma unroll
                for (int n = 0; n < 4; ++n) mma8(d[m][n], al[m], bh[n]);
            #pragma unroll
            for (int n = 0; n < 4; ++n) bl[n] = *(const uint2*)(bb + n*(8*BROW) + koff + 256);
            #pragma unroll
            for (int m = 0; m < 2; ++m)
                #pragma unroll
                for (int n = 0; n < 4; ++n) mma8(d[m][n], ah[m], bl[n]);
        }

        // ---- c2 = D - zs2 - zf2 ----
        const float* zs2raw = (const float*)(sb + OFF_ZS2(buf));
        const float* p1raw  = (const float*)(sb + OFF_P1(buf));
        ull zsp[4], p1p[4];
        const int cbase = cw*32 + 2*q;
        #pragma unroll
        for (int n = 0; n < 4; ++n) {
            zsp[n] = (*(const ull*)(zs2raw + cbase + n*8)) ^ 0x8000000080000000ULL;
            p1p[n] = *(const ull*)(p1raw + cbase + n*8);
        }
        #pragma unroll
        for (int m = 0; m < 2; ++m)
            #pragma unroll
            for (int h = 0; h < 2; ++h) {
                ull rowc = dup2(nzf2row[m*2+h]);
                #pragma unroll
                for (int n = 0; n < 4; ++n) {
                    ull x = pk2(d[m][n][2*h], d[m][n][2*h+1]);
                    ADD2(x, x, zsp[n]);
                    ADD2(x, x, rowc);
                    float2 f = asf2(x);
                    d[m][n][2*h] = f.x; d[m][n][2*h+1] = f.y;
                }
            }

        // ---- row pass ----
        #pragma unroll
        for (int m = 0; m < 2; ++m)
            #pragma unroll
            for (int h = 0; h < 2; ++h) {
                const int s = m*2 + h;
                float bql = bq[s]; int bjl = bj[s];
                #pragma unroll
                for (int n = 0; n < 4; ++n) {
                    float fx = d[m][n][2*h], fy = d[m][n][2*h+1];
                    int jc = j0 + cw*32 + n*8 + 2*q;
                    if (fx > bql) { bql = fx; bjl = jc; }
                    if (fy > bql) { bql = fy; bjl = jc + 1; }
                }
                bq[s] = bql; bj[s] = bjl;
                float ns = fmaf(L2E10, bql, S1g);
                float rsc = fexp2(shift[s] - ns);
                shift[s] = ns;
                { ull rp = dup2(rsc); MUL2(rs2[s], rs2[s], rp); }
                ull msh = dup2(-ns);
                #pragma unroll
                for (int n = 0; n < 4; ++n) {
                    ull c2p = pk2(d[m][n][2*h], d[m][n][2*h+1]);
                    ull tp; ADD2(tp, c2p, p1p[n]);
                    ull tt; FMA2(tt, tp, K.L2, msh);
                    pexp2acc(rs2[s], tt, K);
                }
            }

        // ---- col pass ----
        float cmA[4], cmB[4];
        #pragma unroll
        for (int n = 0; n < 4; ++n) { cmA[n] = -3e38f; cmB[n] = -3e38f; }
        #pragma unroll
        for (int m = 0; m < 2; ++m)
            #pragma unroll
            for (int h = 0; h < 2; ++h)
                #pragma unroll
                for (int n = 0; n < 4; ++n) {
                    cmA[n] = fmaxf(cmA[n], d[m][n][2*h]);
                    cmB[n] = fmaxf(cmB[n], d[m][n][2*h+1]);
                }
        float shA[4], shB[4]; ull nshp[4]; ull csp[4];
        #pragma unroll
        for (int n = 0; n < 4; ++n) {
            shA[n] = fmaf(L2E10, cmA[n], S2g);
            shB[n] = fmaf(L2E10, cmB[n], S2g);
            nshp[n] = pk2(-shA[n], -shB[n]);
            csp[n] = 0ull;
        }
        #pragma unroll
        for (int m = 0; m < 2; ++m)
            #pragma unroll
            for (int h = 0; h < 2; ++h) {
                ull pr = dup2(p2row[m*2+h]);
                #pragma unroll
                for (int n = 0; n < 4; ++n) {
                    ull c2p = pk2(d[m][n][2*h], d[m][n][2*h+1]);
                    ull tp; ADD2(tp, c2p, pr);
                    ull tt; FMA2(tt, tp, K.L2, nshp[n]);
                    pexp2acc(csp[n], tt, K);
                }
            }
        float shc[8], csc[8];
        #pragma unroll
        for (int n = 0; n < 4; ++n) {
            float2 f = asf2(csp[n]);
            shc[2*n] = shA[n];   csc[2*n] = f.x;
            shc[2*n+1] = shB[n]; csc[2*n+1] = f.y;
        }
        #pragma unroll
        for (int mk = 4; mk <= 16; mk <<= 1) {
            #pragma unroll
            for (int s = 0; s < 8; ++s) {
                float om = __shfl_xor_sync(0xffffffffu, shc[s], mk);
                float os = __shfl_xor_sync(0xffffffffu, csc[s], mk);
                if (om > shc[s]) { csc[s] = csc[s]*fexp2(shc[s] - om) + os; shc[s] = om; }
                else             { csc[s] += os*fexp2(om - shc[s]); }
            }
        }
        // write per-rw partials to deferred buffer (no barrier)
        if (g == 0) {
            #pragma unroll
            for (int s = 0; s < 8; ++s) {
                int col = cw*32 + (s >> 1)*8 + 2*q + (s & 1);
                colm[buf*512 + rw*128 + col] = shc[s];
                colsm[buf*512 + rw*128 + col] = csc[s];
            }
        }
    }

    // ---- final tile's col merge + row merge ----
    __syncthreads();
    if (rw == 0 && g == 0) {
        const int pv = (TPC - 1) & 1;
        const int pj0 = cb*CHUNK + (TPC - 1)*BN;
        const float* cmm = colm + pv*512;
        const float* css = colsm + pv*512;
        #pragma unroll
        for (int s = 0; s < 8; ++s) {
            int col = cw*32 + (s >> 1)*8 + 2*q + (s & 1);
            float M = cmm[col], S = css[col];
            #pragma unroll
            for (int r2 = 1; r2 < 4; ++r2) {
                float mm = cmm[r2*128 + col], ss = css[r2*128 + col];
                if (mm > M) { S = S*fexp2(M - mm) + ss; M = mm; }
                else        { S += ss*fexp2(mm - M); }
            }
            g_c_m[rb*Nn + pj0 + col] = M;
            g_c_s[rb*Nn + pj0 + col] = S;
        }
    }

    float rss[4];
    #pragma unroll
    for (int s = 0; s < 4; ++s) { float2 f = asf2(rs2[s]); rss[s] = f.x + f.y; }
    #pragma unroll
    for (int mk = 1; mk <= 2; mk <<= 1) {
        #pragma unroll
        for (int s = 0; s < 4; ++s) {
            float om = __shfl_xor_sync(0xffffffffu, shift[s], mk);
            float os = __shfl_xor_sync(0xffffffffu, rss[s], mk);
            float ob = __shfl_xor_sync(0xffffffffu, bq[s], mk);
            int   oj = __shfl_xor_sync(0xffffffffu, bj[s], mk);
            if (om > shift[s]) { rss[s] = rss[s]*fexp2(shift[s] - om) + os; shift[s] = om; }
            else               { rss[s] += os*fexp2(om - shift[s]); }
            if (ob > bq[s] || (ob == bq[s] && oj < bj[s])) { bq[s] = ob; bj[s] = oj; }
        }
    }
    if (q == 0) {
        #pragma unroll
        for (int s = 0; s < 4; ++s) {
            int row = (rw*2 + (s >> 1))*16 + (s & 1)*8 + g;
            rowm[row*4 + cw] = shift[s];
            rowss[row*4 + cw] = rss[s];
            rowb[row*4 + cw] = bq[s];
            rowj[row*4 + cw] = bj[s];
        }
    }
    __syncthreads();
    if (tid < 128) {
        float m = -3e38f, s = 0.f, bqv = -3e38f; int bjv = 0x7fffffff;
        #pragma unroll
        for (int c = 0; c < 4; ++c) {
            float mm = rowm[tid*4 + c], ss = rowss[tid*4 + c];
            if (mm > m) { s = s*fexp2(m - mm) + ss; m = mm; }
            else        { s += ss*fexp2(mm - m); }
            float bb2 = rowb[tid*4 + c]; int jj = rowj[tid*4 + c];
            if (bb2 > bqv || (bb2 == bqv && jj < bjv)) { bqv = bb2; bjv = jj; }
        }
        g_r_m [cb*Nn + i0 + tid] = m;
        g_r_s [cb*Nn + i0 + tid] = s;
        g_r_bc[cb*Nn + i0 + tid] = bqv;
        g_r_bj[cb*Nn + i0 + tid] = bjv;
    }
}

// ---------------- k3 ----------------
__global__ void k3() {
    int i = blockIdx.x*blockDim.x + threadIdx.x;
    float m = -3e38f, s = 0.f, bqv = -3e38f; int bjv = 0x7fffffff;
    #pragma unroll
    for (int c = 0; c < NCB; ++c) {
        float mm = g_r_m[c*Nn + i], ss = g_r_s[c*Nn + i];
        if (mm > m) { s = s*fexp2(m - mm) + ss; m = mm; }
        else        { s += ss*fexp2(mm - m); }
        float bb = g_r_bc[c*Nn + i]; int jj = g_r_bj[c*Nn + i];
        if (bb > bqv || (bb == bqv && jj < bjv)) { bqv = bb; bjv = jj; }
    }
    g_lse1[i] = LN2*(m + log2f(s)) - logf((float)Nn);
    g_idx[i] = bjv;
    m = -3e38f; s = 0.f;
    #pragma unroll
    for (int r = 0; r < NRB; ++r) {
        float mm = g_c_m[r*Nn + i], ss = g_c_s[r*Nn + i];
        if (mm > m) { s = s*fexp2(m - mm) + ss; m = mm; }
        else        { s += ss*fexp2(mm - m); }
    }
    g_lse2[i] = LN2*(m + log2f(s));
}

// ---------------- k45: block 0 = loss+perplexity, blocks 1..1024 = outputs ----------------
__global__ void k45(const float* __restrict__ z, const float* __restrict__ codebook,
                    float* __restrict__ out) {
    __shared__ int cnt[Nn];
    __shared__ double wred[8*5];
    int tid = threadIdx.x;
    int blk = blockIdx.x;
    if (blk == 0) {
        double v0 = 0, v1 = 0, v2 = 0, v3 = 0;
        for (int i = tid; i < Nn; i += 256) {
            v0 += (double)g_lse1[i];
            v1 += (double)g_phi1[i];
            v2 += (double)g_lse2[i];
            v3 += (double)g_phi2[i];
        }
        for (int i = tid; i < Nn; i += 256) cnt[i] = 0;
        __syncthreads();
        for (int i = tid; i < Nn; i += 256) atomicAdd(&cnt[g_idx[i]], 1);
        __syncthreads();
        double v4 = 0;
        for (int i = tid; i < Nn; i += 256) {
            int c = cnt[i];
            if (c > 0) { float em = (float)c / (float)Nn; v4 += (double)(em * logf(em + 1e-10f)); }
        }
        double vals[5] = {v0, v1, v2, v3, v4};
        int lane = tid & 31, warp = tid >> 5;
        #pragma unroll
        for (int v = 0; v < 5; ++v) {
            double x = vals[v];
            #pragma unroll
            for (int o = 16; o > 0; o >>= 1) x += __shfl_xor_sync(0xffffffffu, x, o);
            if (lane == 0) wred[warp*5 + v] = x;
        }
        __syncthreads();
        if (tid == 0) {
            double t[5] = {0, 0, 0, 0, 0};
            for (int w = 0; w < 8; ++w)
                for (int v = 0; v < 5; ++v) t[v] += wred[w*5 + v];
            double n = (double)Nn;
            double loss1 = (-0.1*t[0] + t[1]) / n;
            double loss2 = (-0.1*t[2]) / n + 0.1*log(n) + t[3]/n;
            out[2*OUTPLANE]     = (float)(0.25*(loss1 + loss2));
            out[2*OUTPLANE + 1] = (float)exp(-t[4]);
        }
        return;
    }
    int o = (blk - 1)*256 + tid;
    int w = o & 15, h = (o >> 4) & 15, c = (o >> 8) & 63, b = o >> 14;
    int i = (h*16 + w)*16 + b;
    out[o] = codebook[(g_idx[i] >> 3)*(2*Dd) + c];
    out[OUTPLANE + o] = z[o];
}

// ---------------- launch ----------------
extern "C" void kernel_launch(void* const* d_in, const int* in_sizes, int n_in,
                              void* d_out, int out_size) {
    const float* z        = (const float*)d_in[0];
    const float* codebook = (const float*)d_in[1];
    const float* w1       = (const float*)d_in[3];
    const float* b1       = (const float*)d_in[4];
    const float* w2       = (const float*)d_in[5];
    const float* b2       = (const float*)d_in[6];
    const float* noise    = (const float*)d_in[7];
    float* out = (float*)d_out;

    cudaFuncSetAttribute(k2, cudaFuncAttributeMaxDynamicSharedMemorySize, SMEM_BYTES);

    k0tr<<<257, 256>>>(z, w1, b1, w2, b2);
    k1<<<Nn/4, 128>>>(codebook, noise);
    {
        dim3 g(NRB, NCB);
        k2<<<g, 512, SMEM_BYTES>>>();
    }
    k3<<<Nn/256, 256>>>();
    k45<<<1025, 256>>>(z, codebook, out);
}

// round 10
// speedup vs baseline: 1.5644x; 1.1094x over previous
#include <cuda_runtime.h>
#include <math.h>
#include <stdint.h>

// ---------------- problem constants ----------------
#define Nn 4096
#define Dd 64
#define HKk 256
#define BM 128
#define BN 128
#define NRB 32
#define NCB 4
#define CHUNK 1024
#define TPC 8
#define OUTPLANE 262144
#define L2E10 14.426950408889634f
#define LN2 0.6931471805599453f

typedef unsigned long long ull;

// ---------------- static device scratch ----------------
__device__ float g_zf[Nn*Dd];
__device__ float g_zf_hi[Nn*Dd], g_zf_lo[Nn*Dd];   // scaled by 2 (A side)
__device__ float g_zsP[Nn*128];                    // B side: [row][hi 64 perm | lo 64 perm]
__device__ float g_zf2[Nn], g_zs2[Nn], g_phi1[Nn], g_phi2[Nn];
__device__ float g_w1m[Dd], g_w2m[Dd], g_b1m, g_b2m;
__device__ unsigned g_aph1, g_aph2;
// transposed partials: rows [i][cb], cols [col][rb]
__device__ float g_r_m[Nn*NCB], g_r_s[Nn*NCB], g_r_bc[Nn*NCB];
__device__ int   g_r_bj[Nn*NCB];
__device__ float g_c_m[Nn*NRB], g_c_s[Nn*NRB];
__device__ int   g_idx[Nn];
__device__ float g_lse1[Nn], g_lse2[Nn];

// ---------------- f32x2 packed helpers ----------------
#define FMA2(d,a,b,c) asm("fma.rn.f32x2 %0, %1, %2, %3;" : "=l"(d) : "l"(a), "l"(b), "l"(c))
#define ADD2(d,a,b)   asm("add.rn.f32x2 %0, %1, %2;"     : "=l"(d) : "l"(a), "l"(b))
#define MUL2(d,a,b)   asm("mul.rn.f32x2 %0, %1, %2;"     : "=l"(d) : "l"(a), "l"(b))

__device__ __forceinline__ ull dup2(float x) {
    ull r; asm("mov.b64 %0, {%1, %1};" : "=l"(r) : "f"(x)); return r;
}
__device__ __forceinline__ ull pk2(float lo, float hi) {
    ull r; asm("mov.b64 %0, {%1, %2};" : "=l"(r) : "f"(lo), "f"(hi)); return r;
}
__device__ __forceinline__ float2 asf2(ull v) {
    float2 f; asm("mov.b64 {%0, %1}, %2;" : "=f"(f.x), "=f"(f.y) : "l"(v)); return f;
}

struct PC { ull MAG, NMAG, NEG1, D3, D2, D1, ONE, L2; };
__device__ __forceinline__ PC make_pc() {
    PC K;
    K.MAG  = dup2(12582912.0f);
    K.NMAG = dup2(-12582912.0f);
    K.NEG1 = dup2(-1.0f);
    K.D3   = dup2(0.0558367f);
    K.D2   = dup2(0.2414282f);
    K.D1   = dup2(0.6931472f);
    K.ONE  = dup2(1.0f);
    K.L2   = dup2(L2E10);
    return K;
}

// acc += exp2(t) (deg-3; args <= 0; underflow clamps to 0)
__device__ __forceinline__ void pexp2acc(ull &acc, ull t, const PC& K) {
    ull tb; ADD2(tb, t, K.MAG);
    ull rr; ADD2(rr, tb, K.NMAG);
    ull f;  FMA2(f, rr, K.NEG1, t);
    ull p = K.D3;
    FMA2(p, p, f, K.D2);
    FMA2(p, p, f, K.D1);
    FMA2(p, p, f, K.ONE);
    int elo = (int)(unsigned)tb         + (127 - 0x4B400000);
    int ehi = (int)(unsigned)(tb >> 32) + (127 - 0x4B400000);
    elo = elo < 0 ? 0 : elo;
    ehi = ehi < 0 ? 0 : ehi;
    ull sc = pk2(__int_as_float(elo << 23), __int_as_float(ehi << 23));
    FMA2(acc, p, sc, acc);
}

// scalar exp2 (deg-5, merges only)
__device__ __forceinline__ float fexp2(float x) {
    float t  = fmaxf(x, -126.0f);
    float tb = t + 12582912.0f;
    int   ni = __float_as_int(tb);
    float r  = tb - 12582912.0f;
    float f  = t - r;
    float p  = 0.00133335581f;
    p = fmaf(p, f, 0.00961812910f);
    p = fmaf(p, f, 0.0555041087f);
    p = fmaf(p, f, 0.240226507f);
    p = fmaf(p, f, 0.693147180f);
    p = fmaf(p, f, 1.0f);
    float sc = __int_as_float((ni + (127 - 0x4B400000)) << 23);
    return p * sc;
}

__device__ __forceinline__ unsigned fenc(float f) {
    unsigned u = __float_as_uint(f);
    return (u & 0x80000000u) ? ~u : (u | 0x80000000u);
}
__device__ __forceinline__ float fdec(unsigned u) {
    return (u & 0x80000000u) ? __uint_as_float(u & 0x7fffffffu) : __uint_as_float(~u);
}

__device__ __forceinline__ float tf32_hi(float x) {
    uint32_t h; asm("cvt.rna.tf32.f32 %0, %1;" : "=r"(h) : "f"(x));
    return __uint_as_float(h);
}

// mma.sync m16n8k8 tf32
__device__ __forceinline__ void mma8(float* d, const uint4& a, const uint2& b) {
    asm("mma.sync.aligned.m16n8k8.row.col.f32.tf32.tf32.f32 "
        "{%0,%1,%2,%3}, {%4,%5,%6,%7}, {%8,%9}, {%0,%1,%2,%3};"
        : "+f"(d[0]), "+f"(d[1]), "+f"(d[2]), "+f"(d[3])
        : "r"(a.x), "r"(a.y), "r"(a.z), "r"(a.w), "r"(b.x), "r"(b.y));
}

// ---------------- cp.async ----------------
#define CPASYNC16(s, g) asm volatile("cp.async.cg.shared.global [%0], [%1], 16;" :: "r"(s), "l"(g))
#define CPASYNC4(s, g)  asm volatile("cp.async.ca.shared.global [%0], [%1], 4;"  :: "r"(s), "l"(g))
#define CP_COMMIT       asm volatile("cp.async.commit_group;" ::: "memory")
#define CP_WAIT(n)      asm volatile("cp.async.wait_group %0;" :: "n"(n) : "memory")

__device__ __forceinline__ uint32_t smem_u32(const void* p) {
    uint32_t a;
    asm("{ .reg .u64 t; cvta.to.shared.u64 t, %1; cvt.u32.u64 %0, t; }" : "=r"(a) : "l"(p));
    return a;
}

// ---------------- smem layout (bytes) ----------------
#define BROW 544
#define BBUF (128*BROW)
#define OFF_A    0
#define OFF_ALO  32768
#define OFF_B    65536
#define OFF_ZS2(b) (204800 + (b)*512)
#define OFF_P1(b)  (205824 + (b)*512)
#define OFF_NZF2 206848
#define OFF_P2   207360
#define OFF_COLM 207872
#define OFF_COLS 211968
#define OFF_ROWM 216064
#define OFF_ROWS 218112
#define OFF_ROWB 220160
#define OFF_ROWJ 222208
#define SMEM_BYTES (224256 + 1024)

// ---------------- k0tr ----------------
__global__ void k0tr(const float* __restrict__ z,
                     const float* __restrict__ w1, const float* __restrict__ b1,
                     const float* __restrict__ w2, const float* __restrict__ b2) {
    __shared__ float tsh[32][33];
    int tid = threadIdx.x;
    int blk = blockIdx.x;
    if (blk == 256) {
        int d = tid >> 2, part = tid & 3;
        float s1 = 0.f, s2 = 0.f;
        for (int k = part*64; k < part*64 + 64; ++k) {
            s1 += w1[d*HKk + k]; s2 += w2[d*HKk + k];
        }
        s1 += __shfl_xor_sync(0xffffffffu, s1, 1);
        s1 += __shfl_xor_sync(0xffffffffu, s1, 2);
        s2 += __shfl_xor_sync(0xffffffffu, s2, 1);
        s2 += __shfl_xor_sync(0xffffffffu, s2, 2);
        if (part == 0) { g_w1m[d] = s1 / (float)HKk; g_w2m[d] = s2 / (float)HKk; }
        if (tid < 64) {
            const float* bb = (tid < 32) ? b1 : b2;
            int l = tid & 31;
            float s = 0.f;
            for (int k = l; k < HKk; k += 32) s += bb[k];
            #pragma unroll
            for (int o = 16; o > 0; o >>= 1) s += __shfl_xor_sync(0xffffffffu, s, o);
            if (l == 0) {
                if (tid < 32) { g_b1m = s / (float)HKk; g_aph1 = 0u; }
                else          { g_b2m = s / (float)HKk; g_aph2 = 0u; }
            }
        }
        return;
    }
    int bx = blk & 7, by = blk >> 3;
    int tx = tid & 31, ty = tid >> 5;
    int x = bx*32 + tx;
    #pragma unroll
    for (int q = 0; q < 4; ++q) {
        int row = by*32 + ty + q*8;
        tsh[ty + q*8][tx] = z[row*256 + x];
    }
    __syncthreads();
    #pragma unroll
    for (int q = 0; q < 4; ++q) {
        int col = bx*32 + ty + q*8;
        int row = by*32 + tx;
        g_zf[col*1024 + row] = tsh[tx][ty + q*8];
    }
}

// ---------------- k1 ----------------
__global__ void k1(const float* __restrict__ codebook, const float* __restrict__ noise) {
    int warp = threadIdx.x >> 5, lane = threadIdx.x & 31;
    int row = blockIdx.x*4 + warp;
    const float* crow = codebook + (row >> 3) * (2*Dd);
    const float* nrow = noise + row*Dd;
    const float* frow = g_zf + row*Dd;
    float zs2 = 0.f, p1 = 0.f, zf2 = 0.f, p2 = 0.f;
    #pragma unroll
    for (int q = 0; q < 2; ++q) {
        int d = lane + q*32;
        float mu  = crow[d];
        float cov = expf(crow[Dd + d]);
        float zs  = mu + cov * nrow[d];
        float zh = tf32_hi(zs);
        int pos = ((d >> 3) << 3) + ((d & 3) << 1) + ((d >> 2) & 1);
        g_zsP[row*128 + pos]      = zh;
        g_zsP[row*128 + 64 + pos] = tf32_hi(zs - zh);
        zs2 += zs*zs;
        p1  += zs * g_w1m[d];
        float zf = frow[d];
        float fh = tf32_hi(zf);
        g_zf_hi[row*Dd + d] = 2.0f * fh;
        g_zf_lo[row*Dd + d] = 2.0f * tf32_hi(zf - fh);
        zf2 += zf*zf;
        p2  += zf * g_w2m[d];
    }
    #pragma unroll
    for (int o = 16; o > 0; o >>= 1) {
        zs2 += __shfl_xor_sync(0xffffffffu, zs2, o);
        p1  += __shfl_xor_sync(0xffffffffu, p1,  o);
        zf2 += __shfl_xor_sync(0xffffffffu, zf2, o);
        p2  += __shfl_xor_sync(0xffffffffu, p2,  o);
    }
    if (lane == 0) {
        float phi1 = p1 + g_b1m, phi2 = p2 + g_b2m;
        g_zs2[row] = zs2;  g_phi1[row] = phi1;
        g_zf2[row] = zf2;  g_phi2[row] = phi2;
        atomicMax(&g_aph1, fenc(phi1));
        atomicMax(&g_aph2, fenc(phi2));
    }
}

// ---------------- k2 ----------------
__global__ void __launch_bounds__(512, 1) k2() {
    extern __shared__ char smem_raw[];
    char* sb = (char*)(((uintptr_t)smem_raw + 1023) & ~(uintptr_t)1023);
    const uint32_t sba = smem_u32(sb);

    const int tid  = threadIdx.x;
    const int lane = tid & 31, wid = tid >> 5;
    const int rw = wid >> 2, cw = wid & 3;
    const int q  = lane & 3,  g  = lane >> 2;
    const int rb = blockIdx.x, cb = blockIdx.y;
    const int i0 = rb * BM;
    const float S1g = L2E10 * fdec(g_aph1);
    const float S2g = L2E10 * fdec(g_aph2);
    const PC K = make_pc();

    float* nzf2s = (float*)(sb + OFF_NZF2);
    float* p2s   = (float*)(sb + OFF_P2);
    float* colm  = (float*)(sb + OFF_COLM);
    float* colsm = (float*)(sb + OFF_COLS);
    float* rowm  = (float*)(sb + OFF_ROWM);
    float* rowss = (float*)(sb + OFF_ROWS);
    float* rowb  = (float*)(sb + OFF_ROWB);
    int*   rowj  = (int*)  (sb + OFF_ROWJ);

    // ---- stage B tile 0 (buf 0) ----
    {
        const int j0 = cb*CHUNK;
        for (int idx = tid; idx < 4096; idx += 512) {
            int row = idx >> 5, ch = idx & 31;
            CPASYNC16(sba + OFF_B + row*BROW + ch*16, g_zsP + (j0 + row)*128 + ch*4);
        }
        if (tid < 128) {
            CPASYNC4(sba + OFF_ZS2(0) + tid*4, g_zs2 + j0 + tid);
            CPASYNC4(sba + OFF_P1(0)  + tid*4, g_phi1 + j0 + tid);
        }
        CP_COMMIT;
    }

    // ---- stage A fragments + row scalars ----
    {
        float4* Ah = (float4*)(sb + OFF_A);
        float4* Al = (float4*)(sb + OFF_ALO);
        for (int t2 = tid; t2 < 2048; t2 += 512) {
            int kt = t2 >> 8, mt = (t2 >> 5) & 7, l = t2 & 31;
            int r0 = (i0 + mt*16 + (l >> 2)) * 64;
            int r8 = r0 + 8*64;
            int c0 = kt*8 + (l & 3);
            float4 v;
            v.x = g_zf_hi[r0 + c0];
            v.y = g_zf_hi[r8 + c0];
            v.z = g_zf_hi[r0 + c0 + 4];
            v.w = g_zf_hi[r8 + c0 + 4];
            Ah[t2] = v;
            v.x = g_zf_lo[r0 + c0];
            v.y = g_zf_lo[r8 + c0];
            v.z = g_zf_lo[r0 + c0 + 4];
            v.w = g_zf_lo[r8 + c0 + 4];
            Al[t2] = v;
        }
        if (tid < 128) {
            nzf2s[tid] = -g_zf2[i0 + tid];
            p2s[tid]   = g_phi2[i0 + tid];
        }
    }
    __syncthreads();

    float nzf2row[4], p2row[4];
    #pragma unroll
    for (int m = 0; m < 2; ++m)
        #pragma unroll
        for (int h = 0; h < 2; ++h) {
            int row = (rw*2 + m)*16 + h*8 + g;
            nzf2row[m*2+h] = nzf2s[row];
            p2row[m*2+h]   = p2s[row];
        }

    float bq[4], shift[4]; int bj[4]; ull rs2[4];
    #pragma unroll
    for (int s = 0; s < 4; ++s) { bq[s] = -3e38f; shift[s] = -1e30f; bj[s] = 0x7fffffff; rs2[s] = 0ull; }

    const char* bthread = sb + OFF_B + (cw*32 + g)*BROW;

    for (int t = 0; t < TPC; ++t) {
        const int buf = t & 1;
        const int j0 = cb*CHUNK + t*BN;

        if (t + 1 < TPC) {
            const int nb = (t + 1) & 1;
            const int nj0 = cb*CHUNK + (t + 1)*BN;
            for (int idx = tid; idx < 4096; idx += 512) {
                int row = idx >> 5, ch = idx & 31;
                CPASYNC16(sba + OFF_B + nb*BBUF + row*BROW + ch*16, g_zsP + (nj0 + row)*128 + ch*4);
            }
            if (tid < 128) {
                CPASYNC4(sba + OFF_ZS2(nb) + tid*4, g_zs2 + nj0 + tid);
                CPASYNC4(sba + OFF_P1(nb)  + tid*4, g_phi1 + nj0 + tid);
            }
            CP_COMMIT;
            CP_WAIT(1);
        } else {
            CP_WAIT(0);
        }
        __syncthreads();

        // ---- staggered merge of previous tile's col partials (two-pass, transposed out) ----
        if (t > 0 && rw == 0 && g == 0) {
            const int pv = (t - 1) & 1;
            const int pj0 = cb*CHUNK + (t - 1)*BN;
            const float* cmm = colm + pv*512;
            const float* css = colsm + pv*512;
            #pragma unroll
            for (int s = 0; s < 8; ++s) {
                int col = cw*32 + (s >> 1)*8 + 2*q + (s & 1);
                float m0 = cmm[col], m1 = cmm[128 + col], m2 = cmm[256 + col], m3 = cmm[384 + col];
                float M = fmaxf(fmaxf(m0, m1), fmaxf(m2, m3));
                float S = css[col]*fexp2(m0 - M) + css[128 + col]*fexp2(m1 - M)
                        + css[256 + col]*fexp2(m2 - M) + css[384 + col]*fexp2(m3 - M);
                g_c_m[(pj0 + col)*NRB + rb] = M;
                g_c_s[(pj0 + col)*NRB + rb] = S;
            }
        }

        // ---- GEMM ----
        float d[2][4][4];
        #pragma unroll
        for (int m = 0; m < 2; ++m)
            #pragma unroll
            for (int n = 0; n < 4; ++n)
                #pragma unroll
                for (int e = 0; e < 4; ++e) d[m][n][e] = 0.f;

        const uint4* Ah = (const uint4*)(sb + OFF_A);
        const uint4* Al = (const uint4*)(sb + OFF_ALO);
        const char* bb = bthread + buf*BBUF;

        #pragma unroll
        for (int kt = 0; kt < 8; ++kt) {
            const int koff = kt*32 + q*8;
            uint4 ah[2], al[2];
            uint2 bh[4], bl[4];
            #pragma unroll
            for (int m = 0; m < 2; ++m) ah[m] = Ah[(kt*8 + rw*2 + m)*32 + lane];
            #pragma unroll
            for (int n = 0; n < 4; ++n) bh[n] = *(const uint2*)(bb + n*(8*BROW) + koff);
            #pragma unroll
            for (int m = 0; m < 2; ++m)
                #pragma unroll
                for (int n = 0; n < 4; ++n) mma8(d[m][n], ah[m], bh[n]);
            #pragma unroll
            for (int m = 0; m < 2; ++m) al[m] = Al[(kt*8 + rw*2 + m)*32 + lane];
            #pragma unroll
            for (int m = 0; m < 2; ++m)
                #pragma unroll
                for (int n = 0; n < 4; ++n) mma8(d[m][n], al[m], bh[n]);
            #pragma unroll
            for (int n = 0; n < 4; ++n) bl[n] = *(const uint2*)(bb + n*(8*BROW) + koff + 256);
            #pragma unroll
            for (int m = 0; m < 2; ++m)
                #pragma unroll
                for (int n = 0; n < 4; ++n) mma8(d[m][n], ah[m], bl[n]);
        }

        // ---- c2 = D - zs2 - zf2 ----
        const float* zs2raw = (const float*)(sb + OFF_ZS2(buf));
        const float* p1raw  = (const float*)(sb + OFF_P1(buf));
        ull zsp[4], p1p[4];
        const int cbase = cw*32 + 2*q;
        #pragma unroll
        for (int n = 0; n < 4; ++n) {
            zsp[n] = (*(const ull*)(zs2raw + cbase + n*8)) ^ 0x8000000080000000ULL;
            p1p[n] = *(const ull*)(p1raw + cbase + n*8);
        }
        #pragma unroll
        for (int m = 0; m < 2; ++m)
            #pragma unroll
            for (int h = 0; h < 2; ++h) {
                ull rowc = dup2(nzf2row[m*2+h]);
                #pragma unroll
                for (int n = 0; n < 4; ++n) {
                    ull x = pk2(d[m][n][2*h], d[m][n][2*h+1]);
                    ADD2(x, x, zsp[n]);
                    ADD2(x, x, rowc);
                    float2 f = asf2(x);
                    d[m][n][2*h] = f.x; d[m][n][2*h+1] = f.y;
                }
            }

        // ---- row pass ----
        #pragma unroll
        for (int m = 0; m < 2; ++m)
            #pragma unroll
            for (int h = 0; h < 2; ++h) {
                const int s = m*2 + h;
                float bql = bq[s]; int bjl = bj[s];
                #pragma unroll
                for (int n = 0; n < 4; ++n) {
                    float fx = d[m][n][2*h], fy = d[m][n][2*h+1];
                    int jc = j0 + cw*32 + n*8 + 2*q;
                    if (fx > bql) { bql = fx; bjl = jc; }
                    if (fy > bql) { bql = fy; bjl = jc + 1; }
                }
                bq[s] = bql; bj[s] = bjl;
                float ns = fmaf(L2E10, bql, S1g);
                float rsc = fexp2(shift[s] - ns);
                shift[s] = ns;
                { ull rp = dup2(rsc); MUL2(rs2[s], rs2[s], rp); }
                ull msh = dup2(-ns);
                #pragma unroll
                for (int n = 0; n < 4; ++n) {
                    ull c2p = pk2(d[m][n][2*h], d[m][n][2*h+1]);
                    ull tp; ADD2(tp, c2p, p1p[n]);
                    ull tt; FMA2(tt, tp, K.L2, msh);
                    pexp2acc(rs2[s], tt, K);
                }
            }

        // ---- col pass ----
        float cmA[4], cmB[4];
        #pragma unroll
        for (int n = 0; n < 4; ++n) { cmA[n] = -3e38f; cmB[n] = -3e38f; }
        #pragma unroll
        for (int m = 0; m < 2; ++m)
            #pragma unroll
            for (int h = 0; h < 2; ++h)
                #pragma unroll
                for (int n = 0; n < 4; ++n) {
                    cmA[n] = fmaxf(cmA[n], d[m][n][2*h]);
                    cmB[n] = fmaxf(cmB[n], d[m][n][2*h+1]);
                }
        float shA[4], shB[4]; ull nshp[4]; ull csp[4];
        #pragma unroll
        for (int n = 0; n < 4; ++n) {
            shA[n] = fmaf(L2E10, cmA[n], S2g);
            shB[n] = fmaf(L2E10, cmB[n], S2g);
            nshp[n] = pk2(-shA[n], -shB[n]);
            csp[n] = 0ull;
        }
        #pragma unroll
        for (int m = 0; m < 2; ++m)
            #pragma unroll
            for (int h = 0; h < 2; ++h) {
                ull pr = dup2(p2row[m*2+h]);
                #pragma unroll
                for (int n = 0; n < 4; ++n) {
                    ull c2p = pk2(d[m][n][2*h], d[m][n][2*h+1]);
                    ull tp; ADD2(tp, c2p, pr);
                    ull tt; FMA2(tt, tp, K.L2, nshp[n]);
                    pexp2acc(csp[n], tt, K);
                }
            }
        float shc[8], csc[8];
        #pragma unroll
        for (int n = 0; n < 4; ++n) {
            float2 f = asf2(csp[n]);
            shc[2*n] = shA[n];   csc[2*n] = f.x;
            shc[2*n+1] = shB[n]; csc[2*n+1] = f.y;
        }
        #pragma unroll
        for (int mk = 4; mk <= 16; mk <<= 1) {
            #pragma unroll
            for (int s = 0; s < 8; ++s) {
                float om = __shfl_xor_sync(0xffffffffu, shc[s], mk);
                float os = __shfl_xor_sync(0xffffffffu, csc[s], mk);
                if (om > shc[s]) { csc[s] = csc[s]*fexp2(shc[s] - om) + os; shc[s] = om; }
                else             { csc[s] += os*fexp2(om - shc[s]); }
            }
        }
        if (g == 0) {
            #pragma unroll
            for (int s = 0; s < 8; ++s) {
                int col = cw*32 + (s >> 1)*8 + 2*q + (s & 1);
                colm[buf*512 + rw*128 + col] = shc[s];
                colsm[buf*512 + rw*128 + col] = csc[s];
            }
        }
    }

    // ---- final tile's col merge + row merge ----
    __syncthreads();
    if (rw == 0 && g == 0) {
        const int pv = (TPC - 1) & 1;
        const int pj0 = cb*CHUNK + (TPC - 1)*BN;
        const float* cmm = colm + pv*512;
        const float* css = colsm + pv*512;
        #pragma unroll
        for (int s = 0; s < 8; ++s) {
            int col = cw*32 + (s >> 1)*8 + 2*q + (s & 1);
            float m0 = cmm[col], m1 = cmm[128 + col], m2 = cmm[256 + col], m3 = cmm[384 + col];
            float M = fmaxf(fmaxf(m0, m1), fmaxf(m2, m3));
            float S = css[col]*fexp2(m0 - M) + css[128 + col]*fexp2(m1 - M)
                    + css[256 + col]*fexp2(m2 - M) + css[384 + col]*fexp2(m3 - M);
            g_c_m[(pj0 + col)*NRB + rb] = M;
            g_c_s[(pj0 + col)*NRB + rb] = S;
        }
    }

    float rss[4];
    #pragma unroll
    for (int s = 0; s < 4; ++s) { float2 f = asf2(rs2[s]); rss[s] = f.x + f.y; }
    #pragma unroll
    for (int mk = 1; mk <= 2; mk <<= 1) {
        #pragma unroll
        for (int s = 0; s < 4; ++s) {
            float om = __shfl_xor_sync(0xffffffffu, shift[s], mk);
            float os = __shfl_xor_sync(0xffffffffu, rss[s], mk);
            float ob = __shfl_xor_sync(0xffffffffu, bq[s], mk);
            int   oj = __shfl_xor_sync(0xffffffffu, bj[s], mk);
            if (om > shift[s]) { rss[s] = rss[s]*fexp2(shift[s] - om) + os; shift[s] = om; }
            else               { rss[s] += os*fexp2(om - shift[s]); }
            if (ob > bq[s] || (ob == bq[s] && oj < bj[s])) { bq[s] = ob; bj[s] = oj; }
        }
    }
    if (q == 0) {
        #pragma unroll
        for (int s = 0; s < 4; ++s) {
            int row = (rw*2 + (s >> 1))*16 + (s & 1)*8 + g;
            rowm[row*4 + cw] = shift[s];
            rowss[row*4 + cw] = rss[s];
            rowb[row*4 + cw] = bq[s];
            rowj[row*4 + cw] = bj[s];
        }
    }
    __syncthreads();
    if (tid < 128) {
        float4 mv = *(const float4*)(rowm + tid*4);
        float4 sv = *(const float4*)(rowss + tid*4);
        float M = fmaxf(fmaxf(mv.x, mv.y), fmaxf(mv.z, mv.w));
        float S = sv.x*fexp2(mv.x - M) + sv.y*fexp2(mv.y - M)
                + sv.z*fexp2(mv.z - M) + sv.w*fexp2(mv.w - M);
        float bqv = -3e38f; int bjv = 0x7fffffff;
        #pragma unroll
        for (int c = 0; c < 4; ++c) {
            float bb2 = rowb[tid*4 + c]; int jj = rowj[tid*4 + c];
            if (bb2 > bqv || (bb2 == bqv && jj < bjv)) { bqv = bb2; bjv = jj; }
        }
        g_r_m [(i0 + tid)*NCB + cb] = M;
        g_r_s [(i0 + tid)*NCB + cb] = S;
        g_r_bc[(i0 + tid)*NCB + cb] = bqv;
        g_r_bj[(i0 + tid)*NCB + cb] = bjv;
    }
}

// ---------------- k3: two-pass merges, vectorized loads ----------------
__global__ void k3() {
    int i = blockIdx.x*blockDim.x + threadIdx.x;
    // rows: 4 partials, contiguous
    {
        float4 mv = *(const float4*)(g_r_m + i*4);
        float4 sv = *(const float4*)(g_r_s + i*4);
        float4 bv = *(const float4*)(g_r_bc + i*4);
        int4   jv = *(const int4*)  (g_r_bj + i*4);
        float M = fmaxf(fmaxf(mv.x, mv.y), fmaxf(mv.z, mv.w));
        float S = sv.x*fexp2(mv.x - M) + sv.y*fexp2(mv.y - M)
                + sv.z*fexp2(mv.z - M) + sv.w*fexp2(mv.w - M);
        g_lse1[i] = LN2*(M + log2f(S)) - logf((float)Nn);
        float bqv = bv.x; int bjv = jv.x;
        if (bv.y > bqv || (bv.y == bqv && jv.y < bjv)) { bqv = bv.y; bjv = jv.y; }
        if (bv.z > bqv || (bv.z == bqv && jv.z < bjv)) { bqv = bv.z; bjv = jv.z; }
        if (bv.w > bqv || (bv.w == bqv && jv.w < bjv)) { bqv = bv.w; bjv = jv.w; }
        g_idx[i] = bjv;
    }
    // cols: 32 partials, contiguous; pass 1 max, pass 2 independent exps
    {
        float4 mv[8];
        #pragma unroll
        for (int k = 0; k < 8; ++k) mv[k] = *(const float4*)(g_c_m + i*32 + k*4);
        float M = -3e38f;
        #pragma unroll
        for (int k = 0; k < 8; ++k)
            M = fmaxf(M, fmaxf(fmaxf(mv[k].x, mv[k].y), fmaxf(mv[k].z, mv[k].w)));
        float S = 0.f;
        #pragma unroll
        for (int k = 0; k < 8; ++k) {
            float4 sv = *(const float4*)(g_c_s + i*32 + k*4);
            S += sv.x*fexp2(mv[k].x - M) + sv.y*fexp2(mv[k].y - M)
               + sv.z*fexp2(mv[k].z - M) + sv.w*fexp2(mv[k].w - M);
        }
        g_lse2[i] = LN2*(M + log2f(S));
    }
}

// ---------------- k45 ----------------
__global__ void k45(const float* __restrict__ z, const float* __restrict__ codebook,
                    float* __restrict__ out) {
    __shared__ int cnt[Nn];
    __shared__ double wred[8*5];
    int tid = threadIdx.x;
    int blk = blockIdx.x;
    if (blk == 0) {
        double v0 = 0, v1 = 0, v2 = 0, v3 = 0;
        for (int i = tid; i < Nn; i += 256) {
            v0 += (double)g_lse1[i];
            v1 += (double)g_phi1[i];
            v2 += (double)g_lse2[i];
            v3 += (double)g_phi2[i];
        }
        for (int i = tid; i < Nn; i += 256) cnt[i] = 0;
        __syncthreads();
        for (int i = tid; i < Nn; i += 256) atomicAdd(&cnt[g_idx[i]], 1);
        __syncthreads();
        double v4 = 0;
        for (int i = tid; i < Nn; i += 256) {
            int c = cnt[i];
            if (c > 0) { float em = (float)c / (float)Nn; v4 += (double)(em * logf(em + 1e-10f)); }
        }
        double vals[5] = {v0, v1, v2, v3, v4};
        int lane = tid & 31, warp = tid >> 5;
        #pragma unroll
        for (int v = 0; v < 5; ++v) {
            double x = vals[v];
            #pragma unroll
            for (int o = 16; o > 0; o >>= 1) x += __shfl_xor_sync(0xffffffffu, x, o);
            if (lane == 0) wred[warp*5 + v] = x;
        }
        __syncthreads();
        if (tid == 0) {
            double t[5] = {0, 0, 0, 0, 0};
            for (int w = 0; w < 8; ++w)
                for (int v = 0; v < 5; ++v) t[v] += wred[w*5 + v];
            double n = (double)Nn;
            double loss1 = (-0.1*t[0] + t[1]) / n;
            double loss2 = (-0.1*t[2]) / n + 0.1*log(n) + t[3]/n;
            out[2*OUTPLANE]     = (float)(0.25*(loss1 + loss2));
            out[2*OUTPLANE + 1] = (float)exp(-t[4]);
        }
        return;
    }
    int o = (blk - 1)*256 + tid;
    int w = o & 15, h = (o >> 4) & 15, c = (o >> 8) & 63, b = o >> 14;
    int i = (h*16 + w)*16 + b;
    out[o] = codebook[(g_idx[i] >> 3)*(2*Dd) + c];
    out[OUTPLANE + o] = z[o];
}

// ---------------- launch ----------------
extern "C" void kernel_launch(void* const* d_in, const int* in_sizes, int n_in,
                              void* d_out, int out_size) {
    const float* z        = (const float*)d_in[0];
    const float* codebook = (const float*)d_in[1];
    const float* w1       = (const float*)d_in[3];
    const float* b1       = (const float*)d_in[4];
    const float* w2       = (const float*)d_in[5];
    const float* b2       = (const float*)d_in[6];
    const float* noise    = (const float*)d_in[7];
    float* out = (float*)d_out;

    cudaFuncSetAttribute(k2, cudaFuncAttributeMaxDynamicSharedMemorySize, SMEM_BYTES);

    k0tr<<<257, 256>>>(z, w1, b1, w2, b2);
    k1<<<Nn/4, 128>>>(codebook, noise);
    {
        dim3 g(NRB, NCB);
        k2<<<g, 512, SMEM_BYTES>>>();
    }
    k3<<<Nn/256, 256>>>();
    k45<<<1025, 256>>>(z, codebook, out);
}